// round 10
// baseline (speedup 1.0000x reference)
#include <cuda_runtime.h>
#include <cuda_fp16.h>
#include <math.h>
#include <stdint.h>

// ---------------- problem constants ----------------
#define BNROWS 4096
#define HIDD   1024
#define MLPD   4096

#define INV_0596 1.6778523489932886f
#define RSQRT058 1.3130643285972254f
#define WSCALE   4096.0f
#define INV_WS   (1.0f / 4096.0f)

// ---------------- scratch ----------------
__device__ float g_s_cond[1024];
__device__ float g_s_qkv[1024];
__device__ float g_s_out[1024];
__device__ float g_s_mlp1[1024];
__device__ float g_s_mlp2[4096];
__device__ float g_gain[4 * 1024];
__device__ float g_shift[4 * 1024];
__device__ float g_cpart[16][4][2048];
__device__ float g_pv[BNROWS];
__device__ float g_x1[BNROWS * HIDD];
__device__ float g_ssp[(size_t)BNROWS * 64];
// fp16 buffers
__device__ __half g_xcondh[BNROWS * HIDD];
__device__ __half g_qkvh[BNROWS * 3072];
__device__ __half g_attnh[BNROWS * HIDD];
__device__ __half g_tmph[BNROWS * HIDD];
__device__ __half g_hh[(size_t)BNROWS * MLPD];
__device__ __half g_qh[64 * 1024 * 64];
__device__ __half g_kh[64 * 1024 * 64];
__device__ __half g_vth[64 * 64 * 1024];
// transposed + scaled (x4096) fp16 weights [N][K]
__device__ __half g_wtq[3072 * 1024];
__device__ __half g_wto[1024 * 1024];
__device__ __half g_wt1[4096 * 1024];
__device__ __half g_wt2[1024 * 4096];

// ---------------- helpers ----------------
__device__ __forceinline__ float block_reduce_sum(float v, float* red) {
    __syncthreads();
    #pragma unroll
    for (int o = 16; o > 0; o >>= 1) v += __shfl_xor_sync(0xffffffffu, v, o);
    int t = threadIdx.x;
    if ((t & 31) == 0) red[t >> 5] = v;
    __syncthreads();
    if (t < 32) {
        int nw = blockDim.x >> 5;
        float r = (t < nw) ? red[t] : 0.f;
        #pragma unroll
        for (int o = 16; o > 0; o >>= 1) r += __shfl_xor_sync(0xffffffffu, r, o);
        if (t == 0) red[0] = r;
    }
    __syncthreads();
    return red[0];
}

__device__ __forceinline__ void cp16(uint32_t s, const void* g) {
    asm volatile("cp.async.cg.shared.global [%0], [%1], 16;" :: "r"(s), "l"(g));
}
__device__ __forceinline__ uint32_t smem_u32(const void* p) {
    uint32_t a;
    asm("{ .reg .u64 t; cvta.to.shared.u64 t, %1; cvt.u32.u64 %0, t; }" : "=r"(a) : "l"(p));
    return a;
}
__device__ __forceinline__ void mma_fp16(float* c, const uint32_t* a, const uint32_t* b) {
    asm volatile("mma.sync.aligned.m16n8k16.row.col.f32.f16.f16.f32 "
        "{%0,%1,%2,%3}, {%4,%5,%6,%7}, {%8,%9}, {%0,%1,%2,%3};"
        : "+f"(c[0]), "+f"(c[1]), "+f"(c[2]), "+f"(c[3])
        : "r"(a[0]), "r"(a[1]), "r"(a[2]), "r"(a[3]), "r"(b[0]), "r"(b[1]));
}
__device__ __forceinline__ void ldsm_x4(uint32_t* r, uint32_t addr) {
    asm volatile("ldmatrix.sync.aligned.m8n8.x4.shared.b16 {%0,%1,%2,%3}, [%4];"
        : "=r"(r[0]), "=r"(r[1]), "=r"(r[2]), "=r"(r[3]) : "r"(addr));
}
__device__ __forceinline__ void ldsm_x2(uint32_t* r, uint32_t addr) {
    asm volatile("ldmatrix.sync.aligned.m8n8.x2.shared.b16 {%0,%1}, [%2];"
        : "=r"(r[0]), "=r"(r[1]) : "r"(addr));
}

// ---------------- K0: weight row-norm scales ----------------
__global__ void scales_kernel(const float* __restrict__ wc, const float* __restrict__ wq,
                              const float* __restrict__ wo, const float* __restrict__ w1,
                              const float* __restrict__ w2) {
    int row = blockIdx.x;
    const float* w; int len; float inv_in; float* dst; int r;
    if (row < 1024)      { w = wc; len = 2048; inv_in = 1024.f; dst = g_s_cond; r = row; }
    else if (row < 2048) { w = wq; len = 3072; inv_in = 1024.f; dst = g_s_qkv;  r = row - 1024; }
    else if (row < 3072) { w = wo; len = 1024; inv_in = 1024.f; dst = g_s_out;  r = row - 2048; }
    else if (row < 4096) { w = w1; len = 4096; inv_in = 1024.f; dst = g_s_mlp1; r = row - 3072; }
    else                 { w = w2; len = 1024; inv_in = 4096.f; dst = g_s_mlp2; r = row - 4096; }
    const float* wr = w + (size_t)r * len;
    float ss = 0.f;
    for (int j = threadIdx.x; j < len; j += blockDim.x) { float v = wr[j]; ss += v * v; }
    __shared__ float red[32];
    ss = block_reduce_sum(ss, red);
    if (threadIdx.x == 0) {
        float norm = sqrtf(ss);
        dst[r] = 1.f / ((norm * sqrtf((float)len) + 1e-4f) * sqrtf(inv_in));
    }
}

// ---------------- transpose + scale-fold (x4096) -> fp16 ----------------
__global__ __launch_bounds__(256) void transpose_scale_kernel(const float* __restrict__ W,
                                                              const float* __restrict__ s,
                                                              __half* __restrict__ Wt,
                                                              int K, int N) {
    __shared__ float t[32][33];
    int k0 = blockIdx.y * 32, n0 = blockIdx.x * 32;
    int tx = threadIdx.x & 31, ty = threadIdx.x >> 5;
    #pragma unroll
    for (int i = 0; i < 32; i += 8) {
        int k = k0 + ty + i;
        t[ty + i][tx] = W[(size_t)k * N + n0 + tx] * (s[k] * WSCALE);
    }
    __syncthreads();
    #pragma unroll
    for (int i = 0; i < 32; i += 8)
        Wt[(size_t)(n0 + ty + i) * K + k0 + tx] = __float2half_rn(t[tx][ty + i]);
}

// ---------------- fp16 GEMM 128x256x64, 3-stage, ldmatrix ----------------
#define SROW        36
#define SA_WORDS    (128 * SROW)
#define SB_WORDS    (256 * SROW)
#define STG_WORDS   (SA_WORDS + SB_WORDS)
#define GEMM_SMEM_BYTES (3 * STG_WORDS * 4)
__global__ __launch_bounds__(256, 1)
void gemm_mma_kernel(const __half* __restrict__ A, const __half* __restrict__ Bt,
                     __half* __restrict__ C, float* __restrict__ ssp,
                     int M, int N, int K) {
    extern __shared__ uint32_t smw[];
    int tid = threadIdx.x;
    int wid = tid >> 5, lane = tid & 31;
    int g = lane >> 2, j = lane & 3;
    int wm = wid >> 2, wn = wid & 3;
    int bm = blockIdx.y * 128;
    int bn = blockIdx.x * 256;
    uint32_t sb = smem_u32(smw);

    // ldmatrix lane base offsets (bytes, within stage)
    uint32_t aOff = (uint32_t)(wm * 64 + ((lane >> 3) & 1) * 8 + (lane & 7)) * (SROW * 4)
                    + (lane >> 4) * 16;
    uint32_t bOff = SA_WORDS * 4
                    + (uint32_t)(wn * 64 + (lane & 7)) * (SROW * 4)
                    + ((lane >> 3) & 1) * 16;

    float acc[4][8][4];
    #pragma unroll
    for (int mt = 0; mt < 4; mt++)
        #pragma unroll
        for (int nt = 0; nt < 8; nt++)
            #pragma unroll
            for (int q = 0; q < 4; q++) acc[mt][nt][q] = 0.f;

    const int NC = K >> 6;

    auto load_chunk = [&](int c, int stg) {
        uint32_t sA = sb + stg * (STG_WORDS * 4);
        uint32_t sB = sA + SA_WORDS * 4;
        int kc = c << 6;
        #pragma unroll
        for (int i = 0; i < 4; i++) {
            int seg = tid + 256 * i;
            int row = seg >> 3, k8 = seg & 7;
            cp16(sA + row * (SROW * 4) + k8 * 16, A + (size_t)(bm + row) * K + kc + k8 * 8);
        }
        #pragma unroll
        for (int i = 0; i < 8; i++) {
            int seg = tid + 256 * i;
            int row = seg >> 3, k8 = seg & 7;
            cp16(sB + row * (SROW * 4) + k8 * 16, Bt + (size_t)(bn + row) * K + kc + k8 * 8);
        }
    };

    load_chunk(0, 0);
    asm volatile("cp.async.commit_group;" ::: "memory");
    load_chunk(1, 1);
    asm volatile("cp.async.commit_group;" ::: "memory");

    for (int c = 0; c < NC; c++) {
        if (c < NC - 1) asm volatile("cp.async.wait_group 1;" ::: "memory");
        else            asm volatile("cp.async.wait_group 0;" ::: "memory");
        __syncthreads();

        uint32_t stgBase = sb + (c % 3) * (STG_WORDS * 4);
        #pragma unroll
        for (int ks = 0; ks < 4; ks++) {
            uint32_t af[4][4];
            #pragma unroll
            for (int mt = 0; mt < 4; mt++)
                ldsm_x4(af[mt], stgBase + aOff + mt * 16 * (SROW * 4) + ks * 32);
            #pragma unroll
            for (int nt = 0; nt < 8; nt++) {
                uint32_t bfr[2];
                ldsm_x2(bfr, stgBase + bOff + nt * 8 * (SROW * 4) + ks * 32);
                #pragma unroll
                for (int mt = 0; mt < 4; mt++)
                    mma_fp16(acc[mt][nt], af[mt], bfr);
            }
        }

        if (c + 2 < NC) {
            load_chunk(c + 2, (c + 2) % 3);
            asm volatile("cp.async.commit_group;" ::: "memory");
        }
    }

    #pragma unroll
    for (int mt = 0; mt < 4; mt++) {
        int row = bm + wm * 64 + mt * 16 + g;
        float s0 = 0.f, s1 = 0.f;
        #pragma unroll
        for (int nt = 0; nt < 8; nt++) {
            int col = bn + wn * 64 + nt * 8 + 2 * j;
            float c0 = acc[mt][nt][0] * INV_WS, c1 = acc[mt][nt][1] * INV_WS;
            float c2 = acc[mt][nt][2] * INV_WS, c3 = acc[mt][nt][3] * INV_WS;
            *(__half2*)(C + (size_t)row * N + col) = __floats2half2_rn(c0, c1);
            *(__half2*)(C + (size_t)(row + 8) * N + col) = __floats2half2_rn(c2, c3);
            s0 += c0 * c0 + c1 * c1;
            s1 += c2 * c2 + c3 * c3;
        }
        if (ssp) {
            s0 += __shfl_xor_sync(0xffffffffu, s0, 1);
            s0 += __shfl_xor_sync(0xffffffffu, s0, 2);
            s1 += __shfl_xor_sync(0xffffffffu, s1, 1);
            s1 += __shfl_xor_sync(0xffffffffu, s1, 2);
            if (j == 0) {
                ssp[(size_t)row * 64 + blockIdx.x * 4 + wn] = s0;
                ssp[(size_t)(row + 8) * 64 + blockIdx.x * 4 + wn] = s1;
            }
        }
    }
}

// ---------------- fp16 GEMM 128x128x64 (for N=1024), 3-stage, 2 blocks/SM ----------------
#define S2A_WORDS   (128 * SROW)
#define S2B_WORDS   (128 * SROW)
#define STG2_WORDS  (S2A_WORDS + S2B_WORDS)
#define GEMM2_SMEM_BYTES (3 * STG2_WORDS * 4)
__global__ __launch_bounds__(256, 2)
void gemm_mma128_kernel(const __half* __restrict__ A, const __half* __restrict__ Bt,
                        __half* __restrict__ C, float* __restrict__ ssp,
                        int M, int N, int K) {
    extern __shared__ uint32_t smw[];
    int tid = threadIdx.x;
    int wid = tid >> 5, lane = tid & 31;
    int g = lane >> 2, j = lane & 3;
    int wm = wid >> 1, wn = wid & 1;   // 4M x 2N, warp tile 32x64
    int bm = blockIdx.y * 128;
    int bn = blockIdx.x * 128;
    uint32_t sb = smem_u32(smw);

    uint32_t aOff = (uint32_t)(wm * 32 + ((lane >> 3) & 1) * 8 + (lane & 7)) * (SROW * 4)
                    + (lane >> 4) * 16;
    uint32_t bOff = S2A_WORDS * 4
                    + (uint32_t)(wn * 64 + (lane & 7)) * (SROW * 4)
                    + ((lane >> 3) & 1) * 16;

    float acc[2][8][4];
    #pragma unroll
    for (int mt = 0; mt < 2; mt++)
        #pragma unroll
        for (int nt = 0; nt < 8; nt++)
            #pragma unroll
            for (int q = 0; q < 4; q++) acc[mt][nt][q] = 0.f;

    const int NC = K >> 6;

    auto load_chunk = [&](int c, int stg) {
        uint32_t sA = sb + stg * (STG2_WORDS * 4);
        uint32_t sB = sA + S2A_WORDS * 4;
        int kc = c << 6;
        #pragma unroll
        for (int i = 0; i < 4; i++) {
            int seg = tid + 256 * i;
            int row = seg >> 3, k8 = seg & 7;
            cp16(sA + row * (SROW * 4) + k8 * 16, A + (size_t)(bm + row) * K + kc + k8 * 8);
        }
        #pragma unroll
        for (int i = 0; i < 4; i++) {
            int seg = tid + 256 * i;
            int row = seg >> 3, k8 = seg & 7;
            cp16(sB + row * (SROW * 4) + k8 * 16, Bt + (size_t)(bn + row) * K + kc + k8 * 8);
        }
    };

    load_chunk(0, 0);
    asm volatile("cp.async.commit_group;" ::: "memory");
    load_chunk(1, 1);
    asm volatile("cp.async.commit_group;" ::: "memory");

    for (int c = 0; c < NC; c++) {
        if (c < NC - 1) asm volatile("cp.async.wait_group 1;" ::: "memory");
        else            asm volatile("cp.async.wait_group 0;" ::: "memory");
        __syncthreads();

        uint32_t stgBase = sb + (c % 3) * (STG2_WORDS * 4);
        #pragma unroll
        for (int ks = 0; ks < 4; ks++) {
            uint32_t af[2][4];
            #pragma unroll
            for (int mt = 0; mt < 2; mt++)
                ldsm_x4(af[mt], stgBase + aOff + mt * 16 * (SROW * 4) + ks * 32);
            #pragma unroll
            for (int nt = 0; nt < 8; nt++) {
                uint32_t bfr[2];
                ldsm_x2(bfr, stgBase + bOff + nt * 8 * (SROW * 4) + ks * 32);
                #pragma unroll
                for (int mt = 0; mt < 2; mt++)
                    mma_fp16(acc[mt][nt], af[mt], bfr);
            }
        }

        if (c + 2 < NC) {
            load_chunk(c + 2, (c + 2) % 3);
            asm volatile("cp.async.commit_group;" ::: "memory");
        }
    }

    #pragma unroll
    for (int mt = 0; mt < 2; mt++) {
        int row = bm + wm * 32 + mt * 16 + g;
        float s0 = 0.f, s1 = 0.f;
        #pragma unroll
        for (int nt = 0; nt < 8; nt++) {
            int col = bn + wn * 64 + nt * 8 + 2 * j;
            float c0 = acc[mt][nt][0] * INV_WS, c1 = acc[mt][nt][1] * INV_WS;
            float c2 = acc[mt][nt][2] * INV_WS, c3 = acc[mt][nt][3] * INV_WS;
            *(__half2*)(C + (size_t)row * N + col) = __floats2half2_rn(c0, c1);
            *(__half2*)(C + (size_t)(row + 8) * N + col) = __floats2half2_rn(c2, c3);
            s0 += c0 * c0 + c1 * c1;
            s1 += c2 * c2 + c3 * c3;
        }
        if (ssp) {
            s0 += __shfl_xor_sync(0xffffffffu, s0, 1);
            s0 += __shfl_xor_sync(0xffffffffu, s0, 2);
            s1 += __shfl_xor_sync(0xffffffffu, s1, 1);
            s1 += __shfl_xor_sync(0xffffffffu, s1, 2);
            if (j == 0) {
                ssp[(size_t)row * 64 + blockIdx.x * 2 + wn] = s0;
                ssp[(size_t)(row + 8) * 64 + blockIdx.x * 2 + wn] = s1;
            }
        }
    }
}

// ---------------- K1: conditioning GEMM, split-K + reduce ----------------
__global__ __launch_bounds__(256) void cond_part_kernel(const float* __restrict__ c,
                                                        const float* __restrict__ w_cond) {
    __shared__ float ccs[4][64];
    int tid = threadIdx.x;
    int i0 = blockIdx.y * 64;
    {
        int bb = tid >> 6, ii = tid & 63;
        float v = c[bb * 1024 + i0 + ii];
        float sil = v / (1.f + expf(-v)) * INV_0596;
        ccs[bb][ii] = sil * g_s_cond[i0 + ii];
    }
    __syncthreads();
    int j = blockIdx.x * 256 + tid;
    float a0 = 0.f, a1 = 0.f, a2 = 0.f, a3 = 0.f;
    #pragma unroll 4
    for (int i = 0; i < 64; i++) {
        float w = w_cond[(size_t)(i0 + i) * 2048 + j];
        a0 += ccs[0][i] * w; a1 += ccs[1][i] * w;
        a2 += ccs[2][i] * w; a3 += ccs[3][i] * w;
    }
    g_cpart[blockIdx.y][0][j] = a0;
    g_cpart[blockIdx.y][1][j] = a1;
    g_cpart[blockIdx.y][2][j] = a2;
    g_cpart[blockIdx.y][3][j] = a3;
}

__global__ __launch_bounds__(256) void cond_reduce_kernel() {
    int idx = blockIdx.x * 256 + threadIdx.x;
    int bb = idx >> 11, j = idx & 2047;
    float a = 0.f;
    #pragma unroll
    for (int s = 0; s < 16; s++) a += g_cpart[s][bb][j];
    if (j < 1024) g_gain[bb * 1024 + j] = a;
    else          g_shift[bb * 1024 + (j - 1024)] = a;
}

// ---------------- K2: x_cond -> fp16 ----------------
__global__ __launch_bounds__(256) void xcond_kernel(const float* __restrict__ x) {
    int r = blockIdx.x; int b = r >> 10;
    const float* xr = x + (size_t)r * HIDD;
    int e = threadIdx.x * 4;
    float4 v = *(const float4*)(xr + e);
    float ss = v.x * v.x + v.y * v.y + v.z * v.z + v.w * v.w;
    __shared__ float red[32];
    ss = block_reduce_sum(ss, red);
    float rs = rsqrtf(ss * (1.f / 1024.f) + 1e-4f);
    const float* gn = g_gain + b * 1024; const float* sh = g_shift + b * 1024;
    float o0 = v.x * rs * (1.f + gn[e + 0]) + sh[e + 0];
    float o1 = v.y * rs * (1.f + gn[e + 1]) + sh[e + 1];
    float o2 = v.z * rs * (1.f + gn[e + 2]) + sh[e + 2];
    float o3 = v.w * rs * (1.f + gn[e + 3]) + sh[e + 3];
    __half2* dst = (__half2*)(g_xcondh + (size_t)r * HIDD + e);
    dst[0] = __floats2half2_rn(o0, o1);
    dst[1] = __floats2half2_rn(o2, o3);
}

// ---------------- K3: q/k normalization from fp16 qkv ----------------
__global__ __launch_bounds__(256) void qkvnorm_kernel() {
    int r = blockIdx.x; int b = r >> 10, n = r & 1023;
    const __half* row = g_qkvh + (size_t)r * 3072;
    int t = threadIdx.x, e = t * 4, head = t >> 4;
    float2 q01 = __half22float2(*(const __half2*)(row + e));
    float2 q23 = __half22float2(*(const __half2*)(row + e + 2));
    float2 k01 = __half22float2(*(const __half2*)(row + 1024 + e));
    float2 k23 = __half22float2(*(const __half2*)(row + 1024 + e + 2));
    float2 v01 = __half22float2(*(const __half2*)(row + 2048 + e));
    float2 v23 = __half22float2(*(const __half2*)(row + 2048 + e + 2));
    __shared__ float hq[16], hk[16], hv[16];
    if (t < 16) { hq[t] = 0.f; hk[t] = 0.f; hv[t] = 0.f; }
    __syncthreads();
    float sq = q01.x * q01.x + q01.y * q01.y + q23.x * q23.x + q23.y * q23.y;
    float sk = k01.x * k01.x + k01.y * k01.y + k23.x * k23.x + k23.y * k23.y;
    float sv = v01.x * v01.x + v01.y * v01.y + v23.x * v23.x + v23.y * v23.y;
    atomicAdd(&hq[head], sq); atomicAdd(&hk[head], sk); atomicAdd(&hv[head], sv);
    __syncthreads();
    float tq = 0.f, tk = 0.f, tv = 0.f;
    #pragma unroll
    for (int h = 0; h < 16; h++) { tq += hq[h]; tk += hk[h]; tv += hv[h]; }
    float pq = rsqrtf(tq * (1.f / 1024.f) + 1e-4f);
    float pk = rsqrtf(tk * (1.f / 1024.f) + 1e-4f);
    float pv = rsqrtf(tv * (1.f / 1024.f) + 1e-4f);
    float qs = pq * rsqrtf(pq * pq * hq[head] + 1e-6f) * 0.125f;
    float ks = pk * rsqrtf(pk * pk * hk[head] + 1e-6f);
    if (t == 0) g_pv[r] = pv;
    size_t base = ((size_t)(b * 16 + head) * 1024 + n) * 64 + (e & 63);
    __half2* qd = (__half2*)(g_qh + base);
    __half2* kd = (__half2*)(g_kh + base);
    qd[0] = __floats2half2_rn(q01.x * qs, q01.y * qs);
    qd[1] = __floats2half2_rn(q23.x * qs, q23.y * qs);
    kd[0] = __floats2half2_rn(k01.x * ks, k01.y * ks);
    kd[1] = __floats2half2_rn(k23.x * ks, k23.y * ks);
}

// ---------------- V transpose (fp16 in) -> fp16 [bh][d][n] ----------------
__global__ __launch_bounds__(256) void vtrans_kernel() {
    __shared__ float t[32][33];
    int bh = blockIdx.z; int b = bh >> 4, h = bh & 15;
    int n0 = blockIdx.x * 32, d0 = blockIdx.y * 32;
    int tx = threadIdx.x & 31, ty = threadIdx.x >> 5;
    #pragma unroll
    for (int i = 0; i < 32; i += 8) {
        int n = n0 + ty + i;
        int rowg = b * 1024 + n;
        t[ty + i][tx] = __half2float(g_qkvh[(size_t)rowg * 3072 + 2048 + h * 64 + d0 + tx])
                        * g_pv[rowg];
    }
    __syncthreads();
    #pragma unroll
    for (int i = 0; i < 32; i += 8) {
        int d = d0 + ty + i;
        g_vth[((size_t)bh * 64 + d) * 1024 + n0 + tx] = __float2half_rn(t[tx][ty + i]);
    }
}

// ---------------- K4: flash attention via fp16 mma.sync ----------------
#define AT_SROW 36
#define AT_BUF  (64 * AT_SROW)
#define ATT_SMEM_BYTES (4 * AT_BUF * 4)
__global__ __launch_bounds__(128, 4) void attn_mma_kernel() {
    extern __shared__ uint32_t smw[];
    uint32_t* uQ  = smw;
    uint32_t* uK  = smw + AT_BUF;
    uint32_t* uVt = smw + 2 * AT_BUF;
    uint32_t* uP  = smw + 3 * AT_BUF;

    int tid = threadIdx.x;
    int w = tid >> 5, lane = tid & 31;
    int g = lane >> 2, j = lane & 3;
    int bh = blockIdx.y;
    int n0 = blockIdx.x * 64;
    const __half* qb  = g_qh + ((size_t)bh * 1024 + n0) * 64;
    const __half* kb  = g_kh + (size_t)bh * 1024 * 64;
    const __half* vtb = g_vth + (size_t)bh * 64 * 1024;

    #pragma unroll
    for (int i = 0; i < 4; i++) {
        int seg = tid + 128 * i;
        int row = seg >> 3, k8 = seg & 7;
        *(uint4*)(uQ + row * AT_SROW + k8 * 4) = *(const uint4*)(qb + row * 64 + k8 * 8);
    }

    float accO[8][4];
    #pragma unroll
    for (int nt = 0; nt < 8; nt++)
        #pragma unroll
        for (int q = 0; q < 4; q++) accO[nt][q] = 0.f;
    float mi0 = -INFINITY, mi1 = -INFINITY, li0 = 0.f, li1 = 0.f;

    for (int kt = 0; kt < 16; kt++) {
        __syncthreads();
        const __half* kb0 = kb + (size_t)kt * 64 * 64;
        #pragma unroll
        for (int i = 0; i < 4; i++) {
            int seg = tid + 128 * i;
            int row = seg >> 3, k8 = seg & 7;
            *(uint4*)(uK + row * AT_SROW + k8 * 4) = *(const uint4*)(kb0 + row * 64 + k8 * 8);
            *(uint4*)(uVt + row * AT_SROW + k8 * 4) =
                *(const uint4*)(vtb + row * 1024 + kt * 64 + k8 * 8);
        }
        __syncthreads();

        float accS[8][4];
        #pragma unroll
        for (int nt = 0; nt < 8; nt++)
            #pragma unroll
            for (int q = 0; q < 4; q++) accS[nt][q] = 0.f;
        #pragma unroll
        for (int ks = 0; ks < 4; ks++) {
            int k = ks * 8;
            uint32_t a[4];
            int r0 = (w * 16 + g) * AT_SROW, r1 = (w * 16 + g + 8) * AT_SROW;
            a[0] = uQ[r0 + k + j];
            a[1] = uQ[r1 + k + j];
            a[2] = uQ[r0 + k + j + 4];
            a[3] = uQ[r1 + k + j + 4];
            #pragma unroll
            for (int nt = 0; nt < 8; nt++) {
                uint32_t bfr[2];
                bfr[0] = uK[(nt * 8 + g) * AT_SROW + k + j];
                bfr[1] = uK[(nt * 8 + g) * AT_SROW + k + j + 4];
                mma_fp16(accS[nt], a, bfr);
            }
        }

        float mx0 = -INFINITY, mx1 = -INFINITY;
        #pragma unroll
        for (int nt = 0; nt < 8; nt++) {
            mx0 = fmaxf(mx0, fmaxf(accS[nt][0], accS[nt][1]));
            mx1 = fmaxf(mx1, fmaxf(accS[nt][2], accS[nt][3]));
        }
        mx0 = fmaxf(mx0, __shfl_xor_sync(0xffffffffu, mx0, 1));
        mx0 = fmaxf(mx0, __shfl_xor_sync(0xffffffffu, mx0, 2));
        mx1 = fmaxf(mx1, __shfl_xor_sync(0xffffffffu, mx1, 1));
        mx1 = fmaxf(mx1, __shfl_xor_sync(0xffffffffu, mx1, 2));
        float nm0 = fmaxf(mi0, mx0), nm1 = fmaxf(mi1, mx1);
        float corr0 = __expf(mi0 - nm0), corr1 = __expf(mi1 - nm1);
        float ps0 = 0.f, ps1 = 0.f;
        #pragma unroll
        for (int nt = 0; nt < 8; nt++) {
            float p0 = __expf(accS[nt][0] - nm0);
            float p1 = __expf(accS[nt][1] - nm0);
            float p2 = __expf(accS[nt][2] - nm1);
            float p3 = __expf(accS[nt][3] - nm1);
            accS[nt][0] = p0; accS[nt][1] = p1; accS[nt][2] = p2; accS[nt][3] = p3;
            ps0 += p0 + p1; ps1 += p2 + p3;
        }
        ps0 += __shfl_xor_sync(0xffffffffu, ps0, 1);
        ps0 += __shfl_xor_sync(0xffffffffu, ps0, 2);
        ps1 += __shfl_xor_sync(0xffffffffu, ps1, 1);
        ps1 += __shfl_xor_sync(0xffffffffu, ps1, 2);
        li0 = li0 * corr0 + ps0; mi0 = nm0;
        li1 = li1 * corr1 + ps1; mi1 = nm1;
        #pragma unroll
        for (int nt = 0; nt < 8; nt++) {
            accO[nt][0] *= corr0; accO[nt][1] *= corr0;
            accO[nt][2] *= corr1; accO[nt][3] *= corr1;
        }

        #pragma unroll
        for (int nt = 0; nt < 8; nt++) {
            ((__half2*)uP)[(w * 16 + g) * AT_SROW + nt * 4 + j] =
                __floats2half2_rn(accS[nt][0], accS[nt][1]);
            ((__half2*)uP)[(w * 16 + g + 8) * AT_SROW + nt * 4 + j] =
                __floats2half2_rn(accS[nt][2], accS[nt][3]);
        }
        __syncwarp();

        #pragma unroll
        for (int ks = 0; ks < 4; ks++) {
            int k = ks * 8;
            uint32_t a[4];
            int r0 = (w * 16 + g) * AT_SROW, r1 = (w * 16 + g + 8) * AT_SROW;
            a[0] = uP[r0 + k + j];
            a[1] = uP[r1 + k + j];
            a[2] = uP[r0 + k + j + 4];
            a[3] = uP[r1 + k + j + 4];
            #pragma unroll
            for (int nt = 0; nt < 8; nt++) {
                uint32_t bfr[2];
                bfr[0] = uVt[(nt * 8 + g) * AT_SROW + k + j];
                bfr[1] = uVt[(nt * 8 + g) * AT_SROW + k + j + 4];
                mma_fp16(accO[nt], a, bfr);
            }
        }
    }

    float inv0 = 1.f / li0, inv1 = 1.f / li1;
    int b = bh >> 4, h = bh & 15;
    int row0 = b * 1024 + n0 + w * 16 + g;
    #pragma unroll
    for (int nt = 0; nt < 8; nt++) {
        int col = h * 64 + nt * 8 + 2 * j;
        *(__half2*)(g_attnh + (size_t)row0 * HIDD + col) =
            __floats2half2_rn(accO[nt][0] * inv0, accO[nt][1] * inv0);
        *(__half2*)(g_attnh + (size_t)(row0 + 8) * HIDD + col) =
            __floats2half2_rn(accO[nt][2] * inv1, accO[nt][3] * inv1);
    }
}

// ---------------- K5: attn epilogue + residual + second x_cond ----------------
__global__ __launch_bounds__(256) void post_attn_kernel(const float* __restrict__ x,
                                                        const float* __restrict__ attn_gain) {
    int r = blockIdx.x, b = r >> 10;
    int e = threadIdx.x * 4;
    const __half* yr = g_tmph + (size_t)r * HIDD;
    float2 y01 = __half22float2(*(const __half2*)(yr + e));
    float2 y23 = __half22float2(*(const __half2*)(yr + e + 2));
    float ss = 0.f;
    const float* sp = g_ssp + (size_t)r * 64;
    #pragma unroll
    for (int p = 0; p < 16; p++) ss += sp[p];
    float py = rsqrtf(ss * (1.f / 1024.f) + 1e-4f) * expf(attn_gain[0]);
    float4 xv = *(const float4*)(x + (size_t)r * HIDD + e);
    float4 x1;
    x1.x = (0.7f * xv.x + 0.3f * (y01.x * py)) * RSQRT058;
    x1.y = (0.7f * xv.y + 0.3f * (y01.y * py)) * RSQRT058;
    x1.z = (0.7f * xv.z + 0.3f * (y23.x * py)) * RSQRT058;
    x1.w = (0.7f * xv.w + 0.3f * (y23.y * py)) * RSQRT058;
    *(float4*)(g_x1 + (size_t)r * HIDD + e) = x1;
    __shared__ float red[32];
    float ss1 = x1.x * x1.x + x1.y * x1.y + x1.z * x1.z + x1.w * x1.w;
    ss1 = block_reduce_sum(ss1, red);
    float p1 = rsqrtf(ss1 * (1.f / 1024.f) + 1e-4f);
    const float* gn = g_gain + b * 1024; const float* sh = g_shift + b * 1024;
    float o0 = x1.x * p1 * (1.f + gn[e + 0]) + sh[e + 0];
    float o1 = x1.y * p1 * (1.f + gn[e + 1]) + sh[e + 1];
    float o2 = x1.z * p1 * (1.f + gn[e + 2]) + sh[e + 2];
    float o3 = x1.w * p1 * (1.f + gn[e + 3]) + sh[e + 3];
    __half2* dst = (__half2*)(g_xcondh + (size_t)r * HIDD + e);
    dst[0] = __floats2half2_rn(o0, o1);
    dst[1] = __floats2half2_rn(o2, o3);
}

// ---------------- K6: MLP hidden activation (in-place fp16) ----------------
__global__ __launch_bounds__(256) void mlp_act_kernel() {
    int r = blockIdx.x;
    __half* row = g_hh + (size_t)r * MLPD;
    float ss = 0.f;
    const float* sp = g_ssp + (size_t)r * 64;
    #pragma unroll
    for (int p = 0; p < 64; p++) ss += sp[p];
    float ps = rsqrtf(ss * (1.f / 4096.f) + 1e-4f);
    int e = threadIdx.x * 16;
    uint4 d0 = *(const uint4*)(row + e);
    uint4 d1 = *(const uint4*)(row + e + 8);
    __half2* h0 = (__half2*)&d0;
    __half2* h1 = (__half2*)&d1;
    #pragma unroll
    for (int i = 0; i < 4; i++) {
        float2 a = __half22float2(h0[i]);
        float2 bq = __half22float2(h1[i]);
        float u0 = a.x * ps, u1 = a.y * ps, u2 = bq.x * ps, u3 = bq.y * ps;
        h0[i] = __floats2half2_rn(u0 / (1.f + expf(-u0)) * INV_0596,
                                  u1 / (1.f + expf(-u1)) * INV_0596);
        h1[i] = __floats2half2_rn(u2 / (1.f + expf(-u2)) * INV_0596,
                                  u3 / (1.f + expf(-u3)) * INV_0596);
    }
    *(uint4*)(row + e) = d0;
    *(uint4*)(row + e + 8) = d1;
}

// ---------------- K7: final epilogue ----------------
__global__ __launch_bounds__(256) void final_kernel(const float* __restrict__ mlp_gain,
                                                    float* __restrict__ out) {
    int r = blockIdx.x;
    int e = threadIdx.x * 4;
    const __half* yr = g_tmph + (size_t)r * HIDD;
    float2 y01 = __half22float2(*(const __half2*)(yr + e));
    float2 y23 = __half22float2(*(const __half2*)(yr + e + 2));
    float ss = 0.f;
    const float* sp = g_ssp + (size_t)r * 64;
    #pragma unroll
    for (int p = 0; p < 16; p++) ss += sp[p];
    float pm = rsqrtf(ss * (1.f / 1024.f) + 1e-4f) * expf(mlp_gain[0]);
    float4 x1 = *(const float4*)(g_x1 + (size_t)r * HIDD + e);
    float4 o;
    o.x = (0.7f * x1.x + 0.3f * (y01.x * pm)) * RSQRT058;
    o.y = (0.7f * x1.y + 0.3f * (y01.y * pm)) * RSQRT058;
    o.z = (0.7f * x1.z + 0.3f * (y23.x * pm)) * RSQRT058;
    o.w = (0.7f * x1.w + 0.3f * (y23.y * pm)) * RSQRT058;
    *(float4*)(out + (size_t)r * HIDD + e) = o;
}

// ---------------- launch ----------------
extern "C" void kernel_launch(void* const* d_in, const int* in_sizes, int n_in,
                              void* d_out, int out_size) {
    const float* x        = (const float*)d_in[0];
    const float* c        = (const float*)d_in[1];
    const float* w_cond   = (const float*)d_in[2];
    const float* w_qkv    = (const float*)d_in[3];
    const float* w_out    = (const float*)d_in[4];
    const float* w_mlp1   = (const float*)d_in[5];
    const float* w_mlp2   = (const float*)d_in[6];
    const float* attn_gain = (const float*)d_in[7];
    const float* mlp_gain  = (const float*)d_in[8];
    float* out = (float*)d_out;

    void* p;
    cudaGetSymbolAddress(&p, g_xcondh); __half* xcondh = (__half*)p;
    cudaGetSymbolAddress(&p, g_qkvh);   __half* qkvh  = (__half*)p;
    cudaGetSymbolAddress(&p, g_attnh);  __half* attnh = (__half*)p;
    cudaGetSymbolAddress(&p, g_tmph);   __half* tmph  = (__half*)p;
    cudaGetSymbolAddress(&p, g_hh);     __half* hh    = (__half*)p;
    cudaGetSymbolAddress(&p, g_ssp);    float* ssp    = (float*)p;
    cudaGetSymbolAddress(&p, g_s_qkv);  float* sqkv   = (float*)p;
    cudaGetSymbolAddress(&p, g_s_out);  float* sout   = (float*)p;
    cudaGetSymbolAddress(&p, g_s_mlp1); float* smlp1  = (float*)p;
    cudaGetSymbolAddress(&p, g_s_mlp2); float* smlp2  = (float*)p;
    cudaGetSymbolAddress(&p, g_wtq);    __half* wtq   = (__half*)p;
    cudaGetSymbolAddress(&p, g_wto);    __half* wto   = (__half*)p;
    cudaGetSymbolAddress(&p, g_wt1);    __half* wt1   = (__half*)p;
    cudaGetSymbolAddress(&p, g_wt2);    __half* wt2   = (__half*)p;

    cudaFuncSetAttribute(attn_mma_kernel, cudaFuncAttributeMaxDynamicSharedMemorySize,
                         ATT_SMEM_BYTES);
    cudaFuncSetAttribute(gemm_mma_kernel, cudaFuncAttributeMaxDynamicSharedMemorySize,
                         GEMM_SMEM_BYTES);
    cudaFuncSetAttribute(gemm_mma128_kernel, cudaFuncAttributeMaxDynamicSharedMemorySize,
                         GEMM2_SMEM_BYTES);

    scales_kernel<<<8192, 128>>>(w_cond, w_qkv, w_out, w_mlp1, w_mlp2);
    cond_part_kernel<<<dim3(8, 16), 256>>>(c, w_cond);
    cond_reduce_kernel<<<32, 256>>>();
    transpose_scale_kernel<<<dim3(3072 / 32, 1024 / 32), 256>>>(w_qkv, sqkv, wtq, 1024, 3072);
    transpose_scale_kernel<<<dim3(1024 / 32, 1024 / 32), 256>>>(w_out, sout, wto, 1024, 1024);
    transpose_scale_kernel<<<dim3(4096 / 32, 1024 / 32), 256>>>(w_mlp1, smlp1, wt1, 1024, 4096);
    transpose_scale_kernel<<<dim3(1024 / 32, 4096 / 32), 256>>>(w_mlp2, smlp2, wt2, 4096, 1024);

    xcond_kernel<<<4096, 256>>>(x);
    gemm_mma_kernel<<<dim3(12, 32), 256, GEMM_SMEM_BYTES>>>(xcondh, wtq, qkvh, nullptr,
                                                            4096, 3072, 1024);
    qkvnorm_kernel<<<4096, 256>>>();
    vtrans_kernel<<<dim3(32, 2, 64), 256>>>();
    attn_mma_kernel<<<dim3(16, 64), 128, ATT_SMEM_BYTES>>>();
    gemm_mma128_kernel<<<dim3(8, 32), 256, GEMM2_SMEM_BYTES>>>(attnh, wto, tmph, ssp,
                                                               4096, 1024, 1024);
    post_attn_kernel<<<4096, 256>>>(x, attn_gain);
    gemm_mma_kernel<<<dim3(16, 32), 256, GEMM_SMEM_BYTES>>>(xcondh, wt1, hh, ssp,
                                                            4096, 4096, 1024);
    mlp_act_kernel<<<4096, 256>>>();
    gemm_mma128_kernel<<<dim3(8, 32), 256, GEMM2_SMEM_BYTES>>>(hh, wt2, tmph, ssp,
                                                               4096, 1024, 4096);
    final_kernel<<<4096, 256>>>(mlp_gain, out);
}

// round 11
// speedup vs baseline: 1.0314x; 1.0314x over previous
#include <cuda_runtime.h>
#include <cuda_fp16.h>
#include <math.h>
#include <stdint.h>

// ---------------- problem constants ----------------
#define BNROWS 4096
#define HIDD   1024
#define MLPD   4096

#define INV_0596 1.6778523489932886f
#define RSQRT058 1.3130643285972254f
#define WSCALE   4096.0f
#define INV_WS   (1.0f / 4096.0f)

// ---------------- scratch ----------------
__device__ float g_s_cond[1024];
__device__ float g_s_qkv[1024];
__device__ float g_s_out[1024];
__device__ float g_s_mlp1[1024];
__device__ float g_s_mlp2[4096];
__device__ float g_gain[4 * 1024];
__device__ float g_shift[4 * 1024];
__device__ float g_cpart[16][4][2048];
__device__ float g_pv[BNROWS];
__device__ float g_x1[BNROWS * HIDD];
__device__ float g_ssp[(size_t)BNROWS * 64];
// fp16 buffers
__device__ __half g_xcondh[BNROWS * HIDD];
__device__ __half g_qkvh[BNROWS * 3072];
__device__ __half g_attnh[BNROWS * HIDD];
__device__ __half g_tmph[BNROWS * HIDD];
__device__ __half g_hh[(size_t)BNROWS * MLPD];
__device__ __half g_qh[64 * 1024 * 64];
__device__ __half g_kh[64 * 1024 * 64];
__device__ __half g_vth[64 * 64 * 1024];
// transposed + scaled (x4096) fp16 weights [N][K]
__device__ __half g_wtq[3072 * 1024];
__device__ __half g_wto[1024 * 1024];
__device__ __half g_wt1[4096 * 1024];
__device__ __half g_wt2[1024 * 4096];

// ---------------- helpers ----------------
__device__ __forceinline__ float block_reduce_sum(float v, float* red) {
    __syncthreads();
    #pragma unroll
    for (int o = 16; o > 0; o >>= 1) v += __shfl_xor_sync(0xffffffffu, v, o);
    int t = threadIdx.x;
    if ((t & 31) == 0) red[t >> 5] = v;
    __syncthreads();
    if (t < 32) {
        int nw = blockDim.x >> 5;
        float r = (t < nw) ? red[t] : 0.f;
        #pragma unroll
        for (int o = 16; o > 0; o >>= 1) r += __shfl_xor_sync(0xffffffffu, r, o);
        if (t == 0) red[0] = r;
    }
    __syncthreads();
    return red[0];
}

__device__ __forceinline__ void cp16(uint32_t s, const void* g) {
    asm volatile("cp.async.cg.shared.global [%0], [%1], 16;" :: "r"(s), "l"(g));
}
__device__ __forceinline__ uint32_t smem_u32(const void* p) {
    uint32_t a;
    asm("{ .reg .u64 t; cvta.to.shared.u64 t, %1; cvt.u32.u64 %0, t; }" : "=r"(a) : "l"(p));
    return a;
}
__device__ __forceinline__ void mma_fp16(float* c, const uint32_t* a, const uint32_t* b) {
    asm volatile("mma.sync.aligned.m16n8k16.row.col.f32.f16.f16.f32 "
        "{%0,%1,%2,%3}, {%4,%5,%6,%7}, {%8,%9}, {%0,%1,%2,%3};"
        : "+f"(c[0]), "+f"(c[1]), "+f"(c[2]), "+f"(c[3])
        : "r"(a[0]), "r"(a[1]), "r"(a[2]), "r"(a[3]), "r"(b[0]), "r"(b[1]));
}

// ---------------- K0: weight row-norm scales ----------------
__global__ void scales_kernel(const float* __restrict__ wc, const float* __restrict__ wq,
                              const float* __restrict__ wo, const float* __restrict__ w1,
                              const float* __restrict__ w2) {
    int row = blockIdx.x;
    const float* w; int len; float inv_in; float* dst; int r;
    if (row < 1024)      { w = wc; len = 2048; inv_in = 1024.f; dst = g_s_cond; r = row; }
    else if (row < 2048) { w = wq; len = 3072; inv_in = 1024.f; dst = g_s_qkv;  r = row - 1024; }
    else if (row < 3072) { w = wo; len = 1024; inv_in = 1024.f; dst = g_s_out;  r = row - 2048; }
    else if (row < 4096) { w = w1; len = 4096; inv_in = 1024.f; dst = g_s_mlp1; r = row - 3072; }
    else                 { w = w2; len = 1024; inv_in = 4096.f; dst = g_s_mlp2; r = row - 4096; }
    const float* wr = w + (size_t)r * len;
    float ss = 0.f;
    for (int j = threadIdx.x; j < len; j += blockDim.x) { float v = wr[j]; ss += v * v; }
    __shared__ float red[32];
    ss = block_reduce_sum(ss, red);
    if (threadIdx.x == 0) {
        float norm = sqrtf(ss);
        dst[r] = 1.f / ((norm * sqrtf((float)len) + 1e-4f) * sqrtf(inv_in));
    }
}

// ---------------- transpose + scale-fold (x4096) -> fp16 ----------------
__global__ __launch_bounds__(256) void transpose_scale_kernel(const float* __restrict__ W,
                                                              const float* __restrict__ s,
                                                              __half* __restrict__ Wt,
                                                              int K, int N) {
    __shared__ float t[32][33];
    int k0 = blockIdx.y * 32, n0 = blockIdx.x * 32;
    int tx = threadIdx.x & 31, ty = threadIdx.x >> 5;
    #pragma unroll
    for (int i = 0; i < 32; i += 8) {
        int k = k0 + ty + i;
        t[ty + i][tx] = W[(size_t)k * N + n0 + tx] * (s[k] * WSCALE);
    }
    __syncthreads();
    #pragma unroll
    for (int i = 0; i < 32; i += 8)
        Wt[(size_t)(n0 + ty + i) * K + k0 + tx] = __float2half_rn(t[tx][ty + i]);
}

// ---------------- fp16 mma.sync GEMM: 128x256x64, 3-stage ----------------
#define SROW        36
#define SA_WORDS    (128 * SROW)
#define SB_WORDS    (256 * SROW)
#define STG_WORDS   (SA_WORDS + SB_WORDS)
#define GEMM_SMEM_BYTES (3 * STG_WORDS * 4)
__global__ __launch_bounds__(256, 1)
void gemm_mma_kernel(const __half* __restrict__ A, const __half* __restrict__ Bt,
                     __half* __restrict__ C, float* __restrict__ ssp,
                     int M, int N, int K) {
    extern __shared__ uint32_t smw[];
    int tid = threadIdx.x;
    int wid = tid >> 5, lane = tid & 31;
    int g = lane >> 2, j = lane & 3;
    int wm = wid >> 2, wn = wid & 3;
    int bm = blockIdx.y * 128;
    int bn = blockIdx.x * 256;
    uint32_t sb = smem_u32(smw);

    float acc[4][8][4];
    #pragma unroll
    for (int mt = 0; mt < 4; mt++)
        #pragma unroll
        for (int nt = 0; nt < 8; nt++)
            #pragma unroll
            for (int q = 0; q < 4; q++) acc[mt][nt][q] = 0.f;

    const int NC = K >> 6;

    auto load_chunk = [&](int c, int stg) {
        uint32_t sA = sb + stg * (STG_WORDS * 4);
        uint32_t sB = sA + SA_WORDS * 4;
        int kc = c << 6;
        #pragma unroll
        for (int i = 0; i < 4; i++) {
            int seg = tid + 256 * i;
            int row = seg >> 3, k8 = seg & 7;
            cp16(sA + row * (SROW * 4) + k8 * 16, A + (size_t)(bm + row) * K + kc + k8 * 8);
        }
        #pragma unroll
        for (int i = 0; i < 8; i++) {
            int seg = tid + 256 * i;
            int row = seg >> 3, k8 = seg & 7;
            cp16(sB + row * (SROW * 4) + k8 * 16, Bt + (size_t)(bn + row) * K + kc + k8 * 8);
        }
    };

    load_chunk(0, 0);
    asm volatile("cp.async.commit_group;" ::: "memory");
    load_chunk(1, 1);
    asm volatile("cp.async.commit_group;" ::: "memory");

    for (int c = 0; c < NC; c++) {
        if (c < NC - 1) asm volatile("cp.async.wait_group 1;" ::: "memory");
        else            asm volatile("cp.async.wait_group 0;" ::: "memory");
        __syncthreads();

        int stg = c % 3;
        const uint32_t* uA = smw + stg * STG_WORDS;
        const uint32_t* uB = smw + stg * STG_WORDS + SA_WORDS;
        #pragma unroll
        for (int ks = 0; ks < 4; ks++) {
            int k = ks * 8;
            uint32_t af[4][4];
            #pragma unroll
            for (int mt = 0; mt < 4; mt++) {
                int row = wm * 64 + mt * 16 + g;
                af[mt][0] = uA[row * SROW + k + j];
                af[mt][1] = uA[(row + 8) * SROW + k + j];
                af[mt][2] = uA[row * SROW + k + j + 4];
                af[mt][3] = uA[(row + 8) * SROW + k + j + 4];
            }
            #pragma unroll
            for (int nt = 0; nt < 8; nt++) {
                int n = wn * 64 + nt * 8 + g;
                uint32_t bfr[2];
                bfr[0] = uB[n * SROW + k + j];
                bfr[1] = uB[n * SROW + k + j + 4];
                #pragma unroll
                for (int mt = 0; mt < 4; mt++)
                    mma_fp16(acc[mt][nt], af[mt], bfr);
            }
        }

        if (c + 2 < NC) {
            load_chunk(c + 2, (c + 2) % 3);
            asm volatile("cp.async.commit_group;" ::: "memory");
        }
    }

    #pragma unroll
    for (int mt = 0; mt < 4; mt++) {
        int row = bm + wm * 64 + mt * 16 + g;
        float s0 = 0.f, s1 = 0.f;
        #pragma unroll
        for (int nt = 0; nt < 8; nt++) {
            int col = bn + wn * 64 + nt * 8 + 2 * j;
            float c0 = acc[mt][nt][0] * INV_WS, c1 = acc[mt][nt][1] * INV_WS;
            float c2 = acc[mt][nt][2] * INV_WS, c3 = acc[mt][nt][3] * INV_WS;
            *(__half2*)(C + (size_t)row * N + col) = __floats2half2_rn(c0, c1);
            *(__half2*)(C + (size_t)(row + 8) * N + col) = __floats2half2_rn(c2, c3);
            s0 += c0 * c0 + c1 * c1;
            s1 += c2 * c2 + c3 * c3;
        }
        if (ssp) {
            s0 += __shfl_xor_sync(0xffffffffu, s0, 1);
            s0 += __shfl_xor_sync(0xffffffffu, s0, 2);
            s1 += __shfl_xor_sync(0xffffffffu, s1, 1);
            s1 += __shfl_xor_sync(0xffffffffu, s1, 2);
            if (j == 0) {
                ssp[(size_t)row * 64 + blockIdx.x * 4 + wn] = s0;
                ssp[(size_t)(row + 8) * 64 + blockIdx.x * 4 + wn] = s1;
            }
        }
    }
}

// ---------------- K1: conditioning GEMM, split-K + reduce ----------------
__global__ __launch_bounds__(256) void cond_part_kernel(const float* __restrict__ c,
                                                        const float* __restrict__ w_cond) {
    __shared__ float ccs[4][64];
    int tid = threadIdx.x;
    int i0 = blockIdx.y * 64;
    {
        int bb = tid >> 6, ii = tid & 63;
        float v = c[bb * 1024 + i0 + ii];
        float sil = v / (1.f + expf(-v)) * INV_0596;
        ccs[bb][ii] = sil * g_s_cond[i0 + ii];
    }
    __syncthreads();
    int j = blockIdx.x * 256 + tid;
    float a0 = 0.f, a1 = 0.f, a2 = 0.f, a3 = 0.f;
    #pragma unroll 4
    for (int i = 0; i < 64; i++) {
        float w = w_cond[(size_t)(i0 + i) * 2048 + j];
        a0 += ccs[0][i] * w; a1 += ccs[1][i] * w;
        a2 += ccs[2][i] * w; a3 += ccs[3][i] * w;
    }
    g_cpart[blockIdx.y][0][j] = a0;
    g_cpart[blockIdx.y][1][j] = a1;
    g_cpart[blockIdx.y][2][j] = a2;
    g_cpart[blockIdx.y][3][j] = a3;
}

__global__ __launch_bounds__(256) void cond_reduce_kernel() {
    int idx = blockIdx.x * 256 + threadIdx.x;
    int bb = idx >> 11, j = idx & 2047;
    float a = 0.f;
    #pragma unroll
    for (int s = 0; s < 16; s++) a += g_cpart[s][bb][j];
    if (j < 1024) g_gain[bb * 1024 + j] = a;
    else          g_shift[bb * 1024 + (j - 1024)] = a;
}

// ---------------- K2: x_cond -> fp16 ----------------
__global__ __launch_bounds__(256) void xcond_kernel(const float* __restrict__ x) {
    int r = blockIdx.x; int b = r >> 10;
    const float* xr = x + (size_t)r * HIDD;
    int e = threadIdx.x * 4;
    float4 v = *(const float4*)(xr + e);
    float ss = v.x * v.x + v.y * v.y + v.z * v.z + v.w * v.w;
    __shared__ float red[32];
    ss = block_reduce_sum(ss, red);
    float rs = rsqrtf(ss * (1.f / 1024.f) + 1e-4f);
    const float* gn = g_gain + b * 1024; const float* sh = g_shift + b * 1024;
    float o0 = v.x * rs * (1.f + gn[e + 0]) + sh[e + 0];
    float o1 = v.y * rs * (1.f + gn[e + 1]) + sh[e + 1];
    float o2 = v.z * rs * (1.f + gn[e + 2]) + sh[e + 2];
    float o3 = v.w * rs * (1.f + gn[e + 3]) + sh[e + 3];
    __half2* dst = (__half2*)(g_xcondh + (size_t)r * HIDD + e);
    dst[0] = __floats2half2_rn(o0, o1);
    dst[1] = __floats2half2_rn(o2, o3);
}

// ---------------- K3: q/k normalization from fp16 qkv ----------------
__global__ __launch_bounds__(256) void qkvnorm_kernel() {
    int r = blockIdx.x; int b = r >> 10, n = r & 1023;
    const __half* row = g_qkvh + (size_t)r * 3072;
    int t = threadIdx.x, e = t * 4, head = t >> 4;
    float2 q01 = __half22float2(*(const __half2*)(row + e));
    float2 q23 = __half22float2(*(const __half2*)(row + e + 2));
    float2 k01 = __half22float2(*(const __half2*)(row + 1024 + e));
    float2 k23 = __half22float2(*(const __half2*)(row + 1024 + e + 2));
    float2 v01 = __half22float2(*(const __half2*)(row + 2048 + e));
    float2 v23 = __half22float2(*(const __half2*)(row + 2048 + e + 2));
    __shared__ float hq[16], hk[16], hv[16];
    if (t < 16) { hq[t] = 0.f; hk[t] = 0.f; hv[t] = 0.f; }
    __syncthreads();
    float sq = q01.x * q01.x + q01.y * q01.y + q23.x * q23.x + q23.y * q23.y;
    float sk = k01.x * k01.x + k01.y * k01.y + k23.x * k23.x + k23.y * k23.y;
    float sv = v01.x * v01.x + v01.y * v01.y + v23.x * v23.x + v23.y * v23.y;
    atomicAdd(&hq[head], sq); atomicAdd(&hk[head], sk); atomicAdd(&hv[head], sv);
    __syncthreads();
    float tq = 0.f, tk = 0.f, tv = 0.f;
    #pragma unroll
    for (int h = 0; h < 16; h++) { tq += hq[h]; tk += hk[h]; tv += hv[h]; }
    float pq = rsqrtf(tq * (1.f / 1024.f) + 1e-4f);
    float pk = rsqrtf(tk * (1.f / 1024.f) + 1e-4f);
    float pv = rsqrtf(tv * (1.f / 1024.f) + 1e-4f);
    float qs = pq * rsqrtf(pq * pq * hq[head] + 1e-6f) * 0.125f;
    float ks = pk * rsqrtf(pk * pk * hk[head] + 1e-6f);
    if (t == 0) g_pv[r] = pv;
    size_t base = ((size_t)(b * 16 + head) * 1024 + n) * 64 + (e & 63);
    __half2* qd = (__half2*)(g_qh + base);
    __half2* kd = (__half2*)(g_kh + base);
    qd[0] = __floats2half2_rn(q01.x * qs, q01.y * qs);
    qd[1] = __floats2half2_rn(q23.x * qs, q23.y * qs);
    kd[0] = __floats2half2_rn(k01.x * ks, k01.y * ks);
    kd[1] = __floats2half2_rn(k23.x * ks, k23.y * ks);
}

// ---------------- V transpose (fp16 in) -> fp16 [bh][d][n] ----------------
__global__ __launch_bounds__(256) void vtrans_kernel() {
    __shared__ float t[32][33];
    int bh = blockIdx.z; int b = bh >> 4, h = bh & 15;
    int n0 = blockIdx.x * 32, d0 = blockIdx.y * 32;
    int tx = threadIdx.x & 31, ty = threadIdx.x >> 5;
    #pragma unroll
    for (int i = 0; i < 32; i += 8) {
        int n = n0 + ty + i;
        int rowg = b * 1024 + n;
        t[ty + i][tx] = __half2float(g_qkvh[(size_t)rowg * 3072 + 2048 + h * 64 + d0 + tx])
                        * g_pv[rowg];
    }
    __syncthreads();
    #pragma unroll
    for (int i = 0; i < 32; i += 8) {
        int d = d0 + ty + i;
        g_vth[((size_t)bh * 64 + d) * 1024 + n0 + tx] = __float2half_rn(t[tx][ty + i]);
    }
}

// ---------------- K4: flash attention, fp16 mma + cp.async double-buffered K/V ----------------
#define AT_SROW 36
#define AT_BUF  (64 * AT_SROW)
#define ATT_SMEM_BYTES (6 * AT_BUF * 4)    // Q, K0, K1, Vt0, Vt1, P = 55296 B
__global__ __launch_bounds__(128, 4) void attn_mma_kernel() {
    extern __shared__ uint32_t smw[];
    uint32_t* uQ = smw;
    uint32_t* uP = smw + 5 * AT_BUF;
    uint32_t sbase = smem_u32(smw);

    int tid = threadIdx.x;
    int w = tid >> 5, lane = tid & 31;
    int g = lane >> 2, j = lane & 3;
    int bh = blockIdx.y;
    int n0 = blockIdx.x * 64;
    const __half* qb  = g_qh + ((size_t)bh * 1024 + n0) * 64;
    const __half* kb  = g_kh + (size_t)bh * 1024 * 64;
    const __half* vtb = g_vth + (size_t)bh * 64 * 1024;

    #pragma unroll
    for (int i = 0; i < 4; i++) {
        int seg = tid + 128 * i;
        int row = seg >> 3, k8 = seg & 7;
        *(uint4*)(uQ + row * AT_SROW + k8 * 4) = *(const uint4*)(qb + row * 64 + k8 * 8);
    }

    auto prefetch = [&](int kt, int bsel) {
        const __half* kb0 = kb + (size_t)kt * 64 * 64;
        uint32_t dK = sbase + (1 + bsel) * (AT_BUF * 4);
        uint32_t dV = sbase + (3 + bsel) * (AT_BUF * 4);
        #pragma unroll
        for (int i = 0; i < 4; i++) {
            int seg = tid + 128 * i;
            int row = seg >> 3, k8 = seg & 7;
            cp16(dK + row * (AT_SROW * 4) + k8 * 16, kb0 + row * 64 + k8 * 8);
            cp16(dV + row * (AT_SROW * 4) + k8 * 16, vtb + row * 1024 + kt * 64 + k8 * 8);
        }
    };

    prefetch(0, 0);
    asm volatile("cp.async.commit_group;" ::: "memory");

    float accO[8][4];
    #pragma unroll
    for (int nt = 0; nt < 8; nt++)
        #pragma unroll
        for (int q = 0; q < 4; q++) accO[nt][q] = 0.f;
    float mi0 = -INFINITY, mi1 = -INFINITY, li0 = 0.f, li1 = 0.f;

    for (int kt = 0; kt < 16; kt++) {
        asm volatile("cp.async.wait_group 0;" ::: "memory");
        __syncthreads();          // tile kt visible; all warps done with tile kt-1 buffers
        if (kt + 1 < 16) {
            prefetch(kt + 1, (kt + 1) & 1);
            asm volatile("cp.async.commit_group;" ::: "memory");
        }
        const uint32_t* uK  = smw + (1 + (kt & 1)) * AT_BUF;
        const uint32_t* uVt = smw + (3 + (kt & 1)) * AT_BUF;

        float accS[8][4];
        #pragma unroll
        for (int nt = 0; nt < 8; nt++)
            #pragma unroll
            for (int q = 0; q < 4; q++) accS[nt][q] = 0.f;
        #pragma unroll
        for (int ks = 0; ks < 4; ks++) {
            int k = ks * 8;
            uint32_t a[4];
            int r0 = (w * 16 + g) * AT_SROW, r1 = (w * 16 + g + 8) * AT_SROW;
            a[0] = uQ[r0 + k + j];
            a[1] = uQ[r1 + k + j];
            a[2] = uQ[r0 + k + j + 4];
            a[3] = uQ[r1 + k + j + 4];
            #pragma unroll
            for (int nt = 0; nt < 8; nt++) {
                uint32_t bfr[2];
                bfr[0] = uK[(nt * 8 + g) * AT_SROW + k + j];
                bfr[1] = uK[(nt * 8 + g) * AT_SROW + k + j + 4];
                mma_fp16(accS[nt], a, bfr);
            }
        }

        float mx0 = -INFINITY, mx1 = -INFINITY;
        #pragma unroll
        for (int nt = 0; nt < 8; nt++) {
            mx0 = fmaxf(mx0, fmaxf(accS[nt][0], accS[nt][1]));
            mx1 = fmaxf(mx1, fmaxf(accS[nt][2], accS[nt][3]));
        }
        mx0 = fmaxf(mx0, __shfl_xor_sync(0xffffffffu, mx0, 1));
        mx0 = fmaxf(mx0, __shfl_xor_sync(0xffffffffu, mx0, 2));
        mx1 = fmaxf(mx1, __shfl_xor_sync(0xffffffffu, mx1, 1));
        mx1 = fmaxf(mx1, __shfl_xor_sync(0xffffffffu, mx1, 2));
        float nm0 = fmaxf(mi0, mx0), nm1 = fmaxf(mi1, mx1);
        float corr0 = __expf(mi0 - nm0), corr1 = __expf(mi1 - nm1);
        float ps0 = 0.f, ps1 = 0.f;
        #pragma unroll
        for (int nt = 0; nt < 8; nt++) {
            float p0 = __expf(accS[nt][0] - nm0);
            float p1 = __expf(accS[nt][1] - nm0);
            float p2 = __expf(accS[nt][2] - nm1);
            float p3 = __expf(accS[nt][3] - nm1);
            accS[nt][0] = p0; accS[nt][1] = p1; accS[nt][2] = p2; accS[nt][3] = p3;
            ps0 += p0 + p1; ps1 += p2 + p3;
        }
        ps0 += __shfl_xor_sync(0xffffffffu, ps0, 1);
        ps0 += __shfl_xor_sync(0xffffffffu, ps0, 2);
        ps1 += __shfl_xor_sync(0xffffffffu, ps1, 1);
        ps1 += __shfl_xor_sync(0xffffffffu, ps1, 2);
        li0 = li0 * corr0 + ps0; mi0 = nm0;
        li1 = li1 * corr1 + ps1; mi1 = nm1;
        #pragma unroll
        for (int nt = 0; nt < 8; nt++) {
            accO[nt][0] *= corr0; accO[nt][1] *= corr0;
            accO[nt][2] *= corr1; accO[nt][3] *= corr1;
        }

        #pragma unroll
        for (int nt = 0; nt < 8; nt++) {
            ((__half2*)uP)[(w * 16 + g) * AT_SROW + nt * 4 + j] =
                __floats2half2_rn(accS[nt][0], accS[nt][1]);
            ((__half2*)uP)[(w * 16 + g + 8) * AT_SROW + nt * 4 + j] =
                __floats2half2_rn(accS[nt][2], accS[nt][3]);
        }
        __syncwarp();

        #pragma unroll
        for (int ks = 0; ks < 4; ks++) {
            int k = ks * 8;
            uint32_t a[4];
            int r0 = (w * 16 + g) * AT_SROW, r1 = (w * 16 + g + 8) * AT_SROW;
            a[0] = uP[r0 + k + j];
            a[1] = uP[r1 + k + j];
            a[2] = uP[r0 + k + j + 4];
            a[3] = uP[r1 + k + j + 4];
            #pragma unroll
            for (int nt = 0; nt < 8; nt++) {
                uint32_t bfr[2];
                bfr[0] = uVt[(nt * 8 + g) * AT_SROW + k + j];
                bfr[1] = uVt[(nt * 8 + g) * AT_SROW + k + j + 4];
                mma_fp16(accO[nt], a, bfr);
            }
        }
    }

    float inv0 = 1.f / li0, inv1 = 1.f / li1;
    int b = bh >> 4, h = bh & 15;
    int row0 = b * 1024 + n0 + w * 16 + g;
    #pragma unroll
    for (int nt = 0; nt < 8; nt++) {
        int col = h * 64 + nt * 8 + 2 * j;
        *(__half2*)(g_attnh + (size_t)row0 * HIDD + col) =
            __floats2half2_rn(accO[nt][0] * inv0, accO[nt][1] * inv0);
        *(__half2*)(g_attnh + (size_t)(row0 + 8) * HIDD + col) =
            __floats2half2_rn(accO[nt][2] * inv1, accO[nt][3] * inv1);
    }
}

// ---------------- K5: attn epilogue + residual + second x_cond ----------------
__global__ __launch_bounds__(256) void post_attn_kernel(const float* __restrict__ x,
                                                        const float* __restrict__ attn_gain) {
    int r = blockIdx.x, b = r >> 10;
    int e = threadIdx.x * 4;
    const __half* yr = g_tmph + (size_t)r * HIDD;
    float2 y01 = __half22float2(*(const __half2*)(yr + e));
    float2 y23 = __half22float2(*(const __half2*)(yr + e + 2));
    float ss = 0.f;
    const float* sp = g_ssp + (size_t)r * 64;
    #pragma unroll
    for (int p = 0; p < 16; p++) ss += sp[p];
    float py = rsqrtf(ss * (1.f / 1024.f) + 1e-4f) * expf(attn_gain[0]);
    float4 xv = *(const float4*)(x + (size_t)r * HIDD + e);
    float4 x1;
    x1.x = (0.7f * xv.x + 0.3f * (y01.x * py)) * RSQRT058;
    x1.y = (0.7f * xv.y + 0.3f * (y01.y * py)) * RSQRT058;
    x1.z = (0.7f * xv.z + 0.3f * (y23.x * py)) * RSQRT058;
    x1.w = (0.7f * xv.w + 0.3f * (y23.y * py)) * RSQRT058;
    *(float4*)(g_x1 + (size_t)r * HIDD + e) = x1;
    __shared__ float red[32];
    float ss1 = x1.x * x1.x + x1.y * x1.y + x1.z * x1.z + x1.w * x1.w;
    ss1 = block_reduce_sum(ss1, red);
    float p1 = rsqrtf(ss1 * (1.f / 1024.f) + 1e-4f);
    const float* gn = g_gain + b * 1024; const float* sh = g_shift + b * 1024;
    float o0 = x1.x * p1 * (1.f + gn[e + 0]) + sh[e + 0];
    float o1 = x1.y * p1 * (1.f + gn[e + 1]) + sh[e + 1];
    float o2 = x1.z * p1 * (1.f + gn[e + 2]) + sh[e + 2];
    float o3 = x1.w * p1 * (1.f + gn[e + 3]) + sh[e + 3];
    __half2* dst = (__half2*)(g_xcondh + (size_t)r * HIDD + e);
    dst[0] = __floats2half2_rn(o0, o1);
    dst[1] = __floats2half2_rn(o2, o3);
}

// ---------------- K6: MLP hidden activation (in-place fp16) ----------------
__global__ __launch_bounds__(256) void mlp_act_kernel() {
    int r = blockIdx.x;
    __half* row = g_hh + (size_t)r * MLPD;
    float ss = 0.f;
    const float* sp = g_ssp + (size_t)r * 64;
    #pragma unroll
    for (int p = 0; p < 64; p++) ss += sp[p];
    float ps = rsqrtf(ss * (1.f / 4096.f) + 1e-4f);
    int e = threadIdx.x * 16;
    uint4 d0 = *(const uint4*)(row + e);
    uint4 d1 = *(const uint4*)(row + e + 8);
    __half2* h0 = (__half2*)&d0;
    __half2* h1 = (__half2*)&d1;
    #pragma unroll
    for (int i = 0; i < 4; i++) {
        float2 a = __half22float2(h0[i]);
        float2 bq = __half22float2(h1[i]);
        float u0 = a.x * ps, u1 = a.y * ps, u2 = bq.x * ps, u3 = bq.y * ps;
        h0[i] = __floats2half2_rn(u0 / (1.f + expf(-u0)) * INV_0596,
                                  u1 / (1.f + expf(-u1)) * INV_0596);
        h1[i] = __floats2half2_rn(u2 / (1.f + expf(-u2)) * INV_0596,
                                  u3 / (1.f + expf(-u3)) * INV_0596);
    }
    *(uint4*)(row + e) = d0;
    *(uint4*)(row + e + 8) = d1;
}

// ---------------- K7: final epilogue ----------------
__global__ __launch_bounds__(256) void final_kernel(const float* __restrict__ mlp_gain,
                                                    float* __restrict__ out) {
    int r = blockIdx.x;
    int e = threadIdx.x * 4;
    const __half* yr = g_tmph + (size_t)r * HIDD;
    float2 y01 = __half22float2(*(const __half2*)(yr + e));
    float2 y23 = __half22float2(*(const __half2*)(yr + e + 2));
    float ss = 0.f;
    const float* sp = g_ssp + (size_t)r * 64;
    #pragma unroll
    for (int p = 0; p < 16; p++) ss += sp[p];
    float pm = rsqrtf(ss * (1.f / 1024.f) + 1e-4f) * expf(mlp_gain[0]);
    float4 x1 = *(const float4*)(g_x1 + (size_t)r * HIDD + e);
    float4 o;
    o.x = (0.7f * x1.x + 0.3f * (y01.x * pm)) * RSQRT058;
    o.y = (0.7f * x1.y + 0.3f * (y01.y * pm)) * RSQRT058;
    o.z = (0.7f * x1.z + 0.3f * (y23.x * pm)) * RSQRT058;
    o.w = (0.7f * x1.w + 0.3f * (y23.y * pm)) * RSQRT058;
    *(float4*)(out + (size_t)r * HIDD + e) = o;
}

// ---------------- launch ----------------
extern "C" void kernel_launch(void* const* d_in, const int* in_sizes, int n_in,
                              void* d_out, int out_size) {
    const float* x        = (const float*)d_in[0];
    const float* c        = (const float*)d_in[1];
    const float* w_cond   = (const float*)d_in[2];
    const float* w_qkv    = (const float*)d_in[3];
    const float* w_out    = (const float*)d_in[4];
    const float* w_mlp1   = (const float*)d_in[5];
    const float* w_mlp2   = (const float*)d_in[6];
    const float* attn_gain = (const float*)d_in[7];
    const float* mlp_gain  = (const float*)d_in[8];
    float* out = (float*)d_out;

    void* p;
    cudaGetSymbolAddress(&p, g_xcondh); __half* xcondh = (__half*)p;
    cudaGetSymbolAddress(&p, g_qkvh);   __half* qkvh  = (__half*)p;
    cudaGetSymbolAddress(&p, g_attnh);  __half* attnh = (__half*)p;
    cudaGetSymbolAddress(&p, g_tmph);   __half* tmph  = (__half*)p;
    cudaGetSymbolAddress(&p, g_hh);     __half* hh    = (__half*)p;
    cudaGetSymbolAddress(&p, g_ssp);    float* ssp    = (float*)p;
    cudaGetSymbolAddress(&p, g_s_qkv);  float* sqkv   = (float*)p;
    cudaGetSymbolAddress(&p, g_s_out);  float* sout   = (float*)p;
    cudaGetSymbolAddress(&p, g_s_mlp1); float* smlp1  = (float*)p;
    cudaGetSymbolAddress(&p, g_s_mlp2); float* smlp2  = (float*)p;
    cudaGetSymbolAddress(&p, g_wtq);    __half* wtq   = (__half*)p;
    cudaGetSymbolAddress(&p, g_wto);    __half* wto   = (__half*)p;
    cudaGetSymbolAddress(&p, g_wt1);    __half* wt1   = (__half*)p;
    cudaGetSymbolAddress(&p, g_wt2);    __half* wt2   = (__half*)p;

    cudaFuncSetAttribute(attn_mma_kernel, cudaFuncAttributeMaxDynamicSharedMemorySize,
                         ATT_SMEM_BYTES);
    cudaFuncSetAttribute(gemm_mma_kernel, cudaFuncAttributeMaxDynamicSharedMemorySize,
                         GEMM_SMEM_BYTES);

    scales_kernel<<<8192, 128>>>(w_cond, w_qkv, w_out, w_mlp1, w_mlp2);
    cond_part_kernel<<<dim3(8, 16), 256>>>(c, w_cond);
    cond_reduce_kernel<<<32, 256>>>();
    transpose_scale_kernel<<<dim3(3072 / 32, 1024 / 32), 256>>>(w_qkv, sqkv, wtq, 1024, 3072);
    transpose_scale_kernel<<<dim3(1024 / 32, 1024 / 32), 256>>>(w_out, sout, wto, 1024, 1024);
    transpose_scale_kernel<<<dim3(4096 / 32, 1024 / 32), 256>>>(w_mlp1, smlp1, wt1, 1024, 4096);
    transpose_scale_kernel<<<dim3(1024 / 32, 4096 / 32), 256>>>(w_mlp2, smlp2, wt2, 4096, 1024);

    xcond_kernel<<<4096, 256>>>(x);
    gemm_mma_kernel<<<dim3(12, 32), 256, GEMM_SMEM_BYTES>>>(xcondh, wtq, qkvh, nullptr,
                                                            4096, 3072, 1024);
    qkvnorm_kernel<<<4096, 256>>>();
    vtrans_kernel<<<dim3(32, 2, 64), 256>>>();
    attn_mma_kernel<<<dim3(16, 64), 128, ATT_SMEM_BYTES>>>();
    gemm_mma_kernel<<<dim3(4, 32), 256, GEMM_SMEM_BYTES>>>(attnh, wto, tmph, ssp,
                                                           4096, 1024, 1024);
    post_attn_kernel<<<4096, 256>>>(x, attn_gain);
    gemm_mma_kernel<<<dim3(16, 32), 256, GEMM_SMEM_BYTES>>>(xcondh, wt1, hh, ssp,
                                                            4096, 4096, 1024);
    mlp_act_kernel<<<4096, 256>>>();
    gemm_mma_kernel<<<dim3(4, 32), 256, GEMM_SMEM_BYTES>>>(hh, wt2, tmph, ssp,
                                                           4096, 1024, 4096);
    final_kernel<<<4096, 256>>>(mlp_gain, out);
}

// round 15
// speedup vs baseline: 1.0360x; 1.0044x over previous
#include <cuda_runtime.h>
#include <cuda_fp16.h>
#include <math.h>
#include <stdint.h>

// ---------------- problem constants ----------------
#define BNROWS 4096
#define HIDD   1024
#define MLPD   4096

#define INV_0596 1.6778523489932886f
#define RSQRT058 1.3130643285972254f
#define WSCALE   4096.0f
#define INV_WS   (1.0f / 4096.0f)

// ---------------- scratch ----------------
__device__ float g_s_cond[1024];
__device__ float g_s_qkv[1024];
__device__ float g_s_out[1024];
__device__ float g_s_mlp1[1024];
__device__ float g_s_mlp2[4096];
__device__ float g_gain[4 * 1024];
__device__ float g_shift[4 * 1024];
__device__ float g_cpart[16][4][2048];
__device__ float g_pv[BNROWS];
__device__ float g_qs[64 * 1024];                 // [bh][n]
__device__ float g_ks[64 * 1024];                 // [bh][n]
__device__ float g_x1[BNROWS * HIDD];
__device__ float g_ssp[(size_t)BNROWS * 64];
// fp16 buffers
__device__ __half g_xcondh[BNROWS * HIDD];
__device__ __half g_qkvh[BNROWS * 3072];
__device__ __half g_attnh[BNROWS * HIDD];
__device__ __half g_tmph[BNROWS * HIDD];
__device__ __half g_hh[(size_t)BNROWS * MLPD];
// transposed + scaled (x4096) fp16 weights [N][K]
__device__ __half g_wtq[3072 * 1024];
__device__ __half g_wto[1024 * 1024];
__device__ __half g_wt1[4096 * 1024];
__device__ __half g_wt2[1024 * 4096];

// ---------------- helpers ----------------
__device__ __forceinline__ float block_reduce_sum(float v, float* red) {
    __syncthreads();
    #pragma unroll
    for (int o = 16; o > 0; o >>= 1) v += __shfl_xor_sync(0xffffffffu, v, o);
    int t = threadIdx.x;
    if ((t & 31) == 0) red[t >> 5] = v;
    __syncthreads();
    if (t < 32) {
        int nw = blockDim.x >> 5;
        float r = (t < nw) ? red[t] : 0.f;
        #pragma unroll
        for (int o = 16; o > 0; o >>= 1) r += __shfl_xor_sync(0xffffffffu, r, o);
        if (t == 0) red[0] = r;
    }
    __syncthreads();
    return red[0];
}

__device__ __forceinline__ void cp16(uint32_t s, const void* g) {
    asm volatile("cp.async.cg.shared.global [%0], [%1], 16;" :: "r"(s), "l"(g));
}
__device__ __forceinline__ uint32_t smem_u32(const void* p) {
    uint32_t a;
    asm("{ .reg .u64 t; cvta.to.shared.u64 t, %1; cvt.u32.u64 %0, t; }" : "=r"(a) : "l"(p));
    return a;
}
__device__ __forceinline__ void mma_fp16(float* c, const uint32_t* a, const uint32_t* b) {
    asm volatile("mma.sync.aligned.m16n8k16.row.col.f32.f16.f16.f32 "
        "{%0,%1,%2,%3}, {%4,%5,%6,%7}, {%8,%9}, {%0,%1,%2,%3};"
        : "+f"(c[0]), "+f"(c[1]), "+f"(c[2]), "+f"(c[3])
        : "r"(a[0]), "r"(a[1]), "r"(a[2]), "r"(a[3]), "r"(b[0]), "r"(b[1]));
}
__device__ __forceinline__ void ldsm_x2_trans(uint32_t* r, uint32_t addr) {
    asm volatile("ldmatrix.sync.aligned.m8n8.x2.trans.shared.b16 {%0,%1}, [%2];"
        : "=r"(r[0]), "=r"(r[1]) : "r"(addr));
}

// ---------------- K0: weight row-norm scales ----------------
__global__ void scales_kernel(const float* __restrict__ wc, const float* __restrict__ wq,
                              const float* __restrict__ wo, const float* __restrict__ w1,
                              const float* __restrict__ w2) {
    int row = blockIdx.x;
    const float* w; int len; float inv_in; float* dst; int r;
    if (row < 1024)      { w = wc; len = 2048; inv_in = 1024.f; dst = g_s_cond; r = row; }
    else if (row < 2048) { w = wq; len = 3072; inv_in = 1024.f; dst = g_s_qkv;  r = row - 1024; }
    else if (row < 3072) { w = wo; len = 1024; inv_in = 1024.f; dst = g_s_out;  r = row - 2048; }
    else if (row < 4096) { w = w1; len = 4096; inv_in = 1024.f; dst = g_s_mlp1; r = row - 3072; }
    else                 { w = w2; len = 1024; inv_in = 4096.f; dst = g_s_mlp2; r = row - 4096; }
    const float* wr = w + (size_t)r * len;
    float ss = 0.f;
    for (int j = threadIdx.x; j < len; j += blockDim.x) { float v = wr[j]; ss += v * v; }
    __shared__ float red[32];
    ss = block_reduce_sum(ss, red);
    if (threadIdx.x == 0) {
        float norm = sqrtf(ss);
        dst[r] = 1.f / ((norm * sqrtf((float)len) + 1e-4f) * sqrtf(inv_in));
    }
}

// ---------------- transpose + scale-fold (x4096) -> fp16 ----------------
__global__ __launch_bounds__(256) void transpose_scale_kernel(const float* __restrict__ W,
                                                              const float* __restrict__ s,
                                                              __half* __restrict__ Wt,
                                                              int K, int N) {
    __shared__ float t[32][33];
    int k0 = blockIdx.y * 32, n0 = blockIdx.x * 32;
    int tx = threadIdx.x & 31, ty = threadIdx.x >> 5;
    #pragma unroll
    for (int i = 0; i < 32; i += 8) {
        int k = k0 + ty + i;
        t[ty + i][tx] = W[(size_t)k * N + n0 + tx] * (s[k] * WSCALE);
    }
    __syncthreads();
    #pragma unroll
    for (int i = 0; i < 32; i += 8)
        Wt[(size_t)(n0 + ty + i) * K + k0 + tx] = __float2half_rn(t[tx][ty + i]);
}

// ---------------- fp16 mma.sync GEMM: 128x256x64, 3-stage ----------------
#define SROW        36
#define SA_WORDS    (128 * SROW)
#define SB_WORDS    (256 * SROW)
#define STG_WORDS   (SA_WORDS + SB_WORDS)
#define GEMM_SMEM_BYTES (3 * STG_WORDS * 4)
__global__ __launch_bounds__(256, 1)
void gemm_mma_kernel(const __half* __restrict__ A, const __half* __restrict__ Bt,
                     __half* __restrict__ C, float* __restrict__ ssp,
                     int M, int N, int K) {
    extern __shared__ uint32_t smw[];
    int tid = threadIdx.x;
    int wid = tid >> 5, lane = tid & 31;
    int g = lane >> 2, j = lane & 3;
    int wm = wid >> 2, wn = wid & 3;
    int bm = blockIdx.y * 128;
    int bn = blockIdx.x * 256;
    uint32_t sb = smem_u32(smw);

    float acc[4][8][4];
    #pragma unroll
    for (int mt = 0; mt < 4; mt++)
        #pragma unroll
        for (int nt = 0; nt < 8; nt++)
            #pragma unroll
            for (int q = 0; q < 4; q++) acc[mt][nt][q] = 0.f;

    const int NC = K >> 6;

    auto load_chunk = [&](int c, int stg) {
        uint32_t sA = sb + stg * (STG_WORDS * 4);
        uint32_t sB = sA + SA_WORDS * 4;
        int kc = c << 6;
        #pragma unroll
        for (int i = 0; i < 4; i++) {
            int seg = tid + 256 * i;
            int row = seg >> 3, k8 = seg & 7;
            cp16(sA + row * (SROW * 4) + k8 * 16, A + (size_t)(bm + row) * K + kc + k8 * 8);
        }
        #pragma unroll
        for (int i = 0; i < 8; i++) {
            int seg = tid + 256 * i;
            int row = seg >> 3, k8 = seg & 7;
            cp16(sB + row * (SROW * 4) + k8 * 16, Bt + (size_t)(bn + row) * K + kc + k8 * 8);
        }
    };

    load_chunk(0, 0);
    asm volatile("cp.async.commit_group;" ::: "memory");
    load_chunk(1, 1);
    asm volatile("cp.async.commit_group;" ::: "memory");

    for (int c = 0; c < NC; c++) {
        if (c < NC - 1) asm volatile("cp.async.wait_group 1;" ::: "memory");
        else            asm volatile("cp.async.wait_group 0;" ::: "memory");
        __syncthreads();

        int stg = c % 3;
        const uint32_t* uA = smw + stg * STG_WORDS;
        const uint32_t* uB = smw + stg * STG_WORDS + SA_WORDS;
        #pragma unroll
        for (int ks = 0; ks < 4; ks++) {
            int k = ks * 8;
            uint32_t af[4][4];
            #pragma unroll
            for (int mt = 0; mt < 4; mt++) {
                int row = wm * 64 + mt * 16 + g;
                af[mt][0] = uA[row * SROW + k + j];
                af[mt][1] = uA[(row + 8) * SROW + k + j];
                af[mt][2] = uA[row * SROW + k + j + 4];
                af[mt][3] = uA[(row + 8) * SROW + k + j + 4];
            }
            #pragma unroll
            for (int nt = 0; nt < 8; nt++) {
                int n = wn * 64 + nt * 8 + g;
                uint32_t bfr[2];
                bfr[0] = uB[n * SROW + k + j];
                bfr[1] = uB[n * SROW + k + j + 4];
                #pragma unroll
                for (int mt = 0; mt < 4; mt++)
                    mma_fp16(acc[mt][nt], af[mt], bfr);
            }
        }

        if (c + 2 < NC) {
            load_chunk(c + 2, (c + 2) % 3);
            asm volatile("cp.async.commit_group;" ::: "memory");
        }
    }

    #pragma unroll
    for (int mt = 0; mt < 4; mt++) {
        int row = bm + wm * 64 + mt * 16 + g;
        float s0 = 0.f, s1 = 0.f;
        #pragma unroll
        for (int nt = 0; nt < 8; nt++) {
            int col = bn + wn * 64 + nt * 8 + 2 * j;
            float c0 = acc[mt][nt][0] * INV_WS, c1 = acc[mt][nt][1] * INV_WS;
            float c2 = acc[mt][nt][2] * INV_WS, c3 = acc[mt][nt][3] * INV_WS;
            *(__half2*)(C + (size_t)row * N + col) = __floats2half2_rn(c0, c1);
            *(__half2*)(C + (size_t)(row + 8) * N + col) = __floats2half2_rn(c2, c3);
            s0 += c0 * c0 + c1 * c1;
            s1 += c2 * c2 + c3 * c3;
        }
        if (ssp) {
            s0 += __shfl_xor_sync(0xffffffffu, s0, 1);
            s0 += __shfl_xor_sync(0xffffffffu, s0, 2);
            s1 += __shfl_xor_sync(0xffffffffu, s1, 1);
            s1 += __shfl_xor_sync(0xffffffffu, s1, 2);
            if (j == 0) {
                ssp[(size_t)row * 64 + blockIdx.x * 4 + wn] = s0;
                ssp[(size_t)(row + 8) * 64 + blockIdx.x * 4 + wn] = s1;
            }
        }
    }
}

// ---------------- K1: conditioning GEMM, split-K + reduce ----------------
__global__ __launch_bounds__(256) void cond_part_kernel(const float* __restrict__ c,
                                                        const float* __restrict__ w_cond) {
    __shared__ float ccs[4][64];
    int tid = threadIdx.x;
    int i0 = blockIdx.y * 64;
    {
        int bb = tid >> 6, ii = tid & 63;
        float v = c[bb * 1024 + i0 + ii];
        float sil = v / (1.f + expf(-v)) * INV_0596;
        ccs[bb][ii] = sil * g_s_cond[i0 + ii];
    }
    __syncthreads();
    int j = blockIdx.x * 256 + tid;
    float a0 = 0.f, a1 = 0.f, a2 = 0.f, a3 = 0.f;
    #pragma unroll 4
    for (int i = 0; i < 64; i++) {
        float w = w_cond[(size_t)(i0 + i) * 2048 + j];
        a0 += ccs[0][i] * w; a1 += ccs[1][i] * w;
        a2 += ccs[2][i] * w; a3 += ccs[3][i] * w;
    }
    g_cpart[blockIdx.y][0][j] = a0;
    g_cpart[blockIdx.y][1][j] = a1;
    g_cpart[blockIdx.y][2][j] = a2;
    g_cpart[blockIdx.y][3][j] = a3;
}

__global__ __launch_bounds__(256) void cond_reduce_kernel() {
    int idx = blockIdx.x * 256 + threadIdx.x;
    int bb = idx >> 11, j = idx & 2047;
    float a = 0.f;
    #pragma unroll
    for (int s = 0; s < 16; s++) a += g_cpart[s][bb][j];
    if (j < 1024) g_gain[bb * 1024 + j] = a;
    else          g_shift[bb * 1024 + (j - 1024)] = a;
}

// ---------------- K2: x_cond -> fp16 ----------------
__global__ __launch_bounds__(256) void xcond_kernel(const float* __restrict__ x) {
    int r = blockIdx.x; int b = r >> 10;
    const float* xr = x + (size_t)r * HIDD;
    int e = threadIdx.x * 4;
    float4 v = *(const float4*)(xr + e);
    float ss = v.x * v.x + v.y * v.y + v.z * v.z + v.w * v.w;
    __shared__ float red[32];
    ss = block_reduce_sum(ss, red);
    float rs = rsqrtf(ss * (1.f / 1024.f) + 1e-4f);
    const float* gn = g_gain + b * 1024; const float* sh = g_shift + b * 1024;
    float o0 = v.x * rs * (1.f + gn[e + 0]) + sh[e + 0];
    float o1 = v.y * rs * (1.f + gn[e + 1]) + sh[e + 1];
    float o2 = v.z * rs * (1.f + gn[e + 2]) + sh[e + 2];
    float o3 = v.w * rs * (1.f + gn[e + 3]) + sh[e + 3];
    __half2* dst = (__half2*)(g_xcondh + (size_t)r * HIDD + e);
    dst[0] = __floats2half2_rn(o0, o1);
    dst[1] = __floats2half2_rn(o2, o3);
}

// ---------------- K3: qkv scale factors only (qs, ks, pv) ----------------
__global__ __launch_bounds__(256) void qkvnorm_kernel() {
    int r = blockIdx.x; int b = r >> 10, n = r & 1023;
    const __half* row = g_qkvh + (size_t)r * 3072;
    int t = threadIdx.x, e = t * 4, head = t >> 4;
    float2 q01 = __half22float2(*(const __half2*)(row + e));
    float2 q23 = __half22float2(*(const __half2*)(row + e + 2));
    float2 k01 = __half22float2(*(const __half2*)(row + 1024 + e));
    float2 k23 = __half22float2(*(const __half2*)(row + 1024 + e + 2));
    float2 v01 = __half22float2(*(const __half2*)(row + 2048 + e));
    float2 v23 = __half22float2(*(const __half2*)(row + 2048 + e + 2));
    __shared__ float hq[16], hk[16], hv[16];
    if (t < 16) { hq[t] = 0.f; hk[t] = 0.f; hv[t] = 0.f; }
    __syncthreads();
    float sq = q01.x * q01.x + q01.y * q01.y + q23.x * q23.x + q23.y * q23.y;
    float sk = k01.x * k01.x + k01.y * k01.y + k23.x * k23.x + k23.y * k23.y;
    float sv = v01.x * v01.x + v01.y * v01.y + v23.x * v23.x + v23.y * v23.y;
    atomicAdd(&hq[head], sq); atomicAdd(&hk[head], sk); atomicAdd(&hv[head], sv);
    __syncthreads();
    float tq = 0.f, tk = 0.f, tv = 0.f;
    #pragma unroll
    for (int h = 0; h < 16; h++) { tq += hq[h]; tk += hk[h]; tv += hv[h]; }
    float pq = rsqrtf(tq * (1.f / 1024.f) + 1e-4f);
    float pk = rsqrtf(tk * (1.f / 1024.f) + 1e-4f);
    float pv = rsqrtf(tv * (1.f / 1024.f) + 1e-4f);
    if (t < 16) {
        float qs = pq * rsqrtf(pq * pq * hq[t] + 1e-6f) * 0.125f;
        float ks = pk * rsqrtf(pk * pk * hk[t] + 1e-6f);
        g_qs[(b * 16 + t) * 1024 + n] = qs;
        g_ks[(b * 16 + t) * 1024 + n] = ks;
    }
    if (t == 0) g_pv[r] = pv;
}

// ---------------- K4: flash attention from raw qkvh, scales applied in-kernel ----------------
#define AT_SROW 36
#define AT_BUF  (64 * AT_SROW)
// layout (words): Q | K0 | K1 | V0 | V1 | P | qss(64f) | kss0 kss1 pvs0 pvs1 (64f each)
#define AT_QSS  (6 * AT_BUF)
#define AT_KSS  (AT_QSS + 64)
#define ATT_SMEM_BYTES ((6 * AT_BUF + 64 + 4 * 64) * 4)
__global__ __launch_bounds__(128, 4) void attn_mma_kernel() {
    extern __shared__ uint32_t smw[];
    uint32_t* uQ = smw;
    uint32_t* uP = smw + 5 * AT_BUF;
    float* qss = (float*)(smw + AT_QSS);
    uint32_t sbase = smem_u32(smw);

    int tid = threadIdx.x;
    int w = tid >> 5, lane = tid & 31;
    int g = lane >> 2, j = lane & 3;
    int bh = blockIdx.y;
    int b = bh >> 4, h = bh & 15;
    int n0 = blockIdx.x * 64;
    const __half* qb = g_qkvh + ((size_t)(b * 1024 + n0)) * 3072 + h * 64;
    const __half* kb = g_qkvh + (size_t)b * 1024 * 3072 + 1024 + h * 64;
    const __half* vb = g_qkvh + (size_t)b * 1024 * 3072 + 2048 + h * 64;

    // Q tile (raw) + per-row q scales
    #pragma unroll
    for (int i = 0; i < 4; i++) {
        int seg = tid + 128 * i;
        int row = seg >> 3, k8 = seg & 7;
        *(uint4*)(uQ + row * AT_SROW + k8 * 4) =
            *(const uint4*)(qb + (size_t)row * 3072 + k8 * 8);
    }
    if (tid < 64) qss[tid] = g_qs[(size_t)bh * 1024 + n0 + tid];

    auto prefetch = [&](int kt, int bsel) {
        uint32_t dK = sbase + (1 + bsel) * (AT_BUF * 4);
        uint32_t dV = sbase + (3 + bsel) * (AT_BUF * 4);
        #pragma unroll
        for (int i = 0; i < 4; i++) {
            int seg = tid + 128 * i;
            int row = seg >> 3, k8 = seg & 7;
            cp16(dK + row * (AT_SROW * 4) + k8 * 16,
                 kb + (size_t)(kt * 64 + row) * 3072 + k8 * 8);
            cp16(dV + row * (AT_SROW * 4) + k8 * 16,
                 vb + (size_t)(kt * 64 + row) * 3072 + k8 * 8);
        }
        uint32_t dks = sbase + (AT_KSS + bsel * 64) * 4;
        uint32_t dpv = sbase + (AT_KSS + (2 + bsel) * 64) * 4;
        if (tid < 16)
            cp16(dks + tid * 16, g_ks + (size_t)bh * 1024 + kt * 64 + tid * 4);
        else if (tid < 32)
            cp16(dpv + (tid - 16) * 16, g_pv + (size_t)b * 1024 + kt * 64 + (tid - 16) * 4);
    };

    prefetch(0, 0);
    asm volatile("cp.async.commit_group;" ::: "memory");

    float accO[8][4];
    #pragma unroll
    for (int nt = 0; nt < 8; nt++)
        #pragma unroll
        for (int q = 0; q < 4; q++) accO[nt][q] = 0.f;
    float mi0 = -INFINITY, mi1 = -INFINITY, li0 = 0.f, li1 = 0.f;

    for (int kt = 0; kt < 16; kt++) {
        asm volatile("cp.async.wait_group 0;" ::: "memory");
        __syncthreads();
        if (kt + 1 < 16) {
            prefetch(kt + 1, (kt + 1) & 1);
            asm volatile("cp.async.commit_group;" ::: "memory");
        }
        int bsel = kt & 1;
        const uint32_t* uK = smw + (1 + bsel) * AT_BUF;
        uint32_t sV = sbase + (3 + bsel) * (AT_BUF * 4);
        const float* kss = (const float*)(smw + AT_KSS + bsel * 64);
        const float* pvs = (const float*)(smw + AT_KSS + (2 + bsel) * 64);

        // S = Qraw @ Kraw^T
        float accS[8][4];
        #pragma unroll
        for (int nt = 0; nt < 8; nt++)
            #pragma unroll
            for (int q = 0; q < 4; q++) accS[nt][q] = 0.f;
        #pragma unroll
        for (int ks = 0; ks < 4; ks++) {
            int k = ks * 8;
            uint32_t a[4];
            int r0 = (w * 16 + g) * AT_SROW, r1 = (w * 16 + g + 8) * AT_SROW;
            a[0] = uQ[r0 + k + j];
            a[1] = uQ[r1 + k + j];
            a[2] = uQ[r0 + k + j + 4];
            a[3] = uQ[r1 + k + j + 4];
            #pragma unroll
            for (int nt = 0; nt < 8; nt++) {
                uint32_t bfr[2];
                bfr[0] = uK[(nt * 8 + g) * AT_SROW + k + j];
                bfr[1] = uK[(nt * 8 + g) * AT_SROW + k + j + 4];
                mma_fp16(accS[nt], a, bfr);
            }
        }

        // apply qs (rows) * ks (cols)
        float qs0 = qss[w * 16 + g], qs1 = qss[w * 16 + g + 8];
        #pragma unroll
        for (int nt = 0; nt < 8; nt++) {
            float2 kv = *(const float2*)(kss + nt * 8 + 2 * j);
            accS[nt][0] *= qs0 * kv.x; accS[nt][1] *= qs0 * kv.y;
            accS[nt][2] *= qs1 * kv.x; accS[nt][3] *= qs1 * kv.y;
        }

        float mx0 = -INFINITY, mx1 = -INFINITY;
        #pragma unroll
        for (int nt = 0; nt < 8; nt++) {
            mx0 = fmaxf(mx0, fmaxf(accS[nt][0], accS[nt][1]));
            mx1 = fmaxf(mx1, fmaxf(accS[nt][2], accS[nt][3]));
        }
        mx0 = fmaxf(mx0, __shfl_xor_sync(0xffffffffu, mx0, 1));
        mx0 = fmaxf(mx0, __shfl_xor_sync(0xffffffffu, mx0, 2));
        mx1 = fmaxf(mx1, __shfl_xor_sync(0xffffffffu, mx1, 1));
        mx1 = fmaxf(mx1, __shfl_xor_sync(0xffffffffu, mx1, 2));
        float nm0 = fmaxf(mi0, mx0), nm1 = fmaxf(mi1, mx1);
        float corr0 = __expf(mi0 - nm0), corr1 = __expf(mi1 - nm1);
        float ps0 = 0.f, ps1 = 0.f;
        #pragma unroll
        for (int nt = 0; nt < 8; nt++) {
            float p0 = __expf(accS[nt][0] - nm0);
            float p1 = __expf(accS[nt][1] - nm0);
            float p2 = __expf(accS[nt][2] - nm1);
            float p3 = __expf(accS[nt][3] - nm1);
            accS[nt][0] = p0; accS[nt][1] = p1; accS[nt][2] = p2; accS[nt][3] = p3;
            ps0 += p0 + p1; ps1 += p2 + p3;
        }
        ps0 += __shfl_xor_sync(0xffffffffu, ps0, 1);
        ps0 += __shfl_xor_sync(0xffffffffu, ps0, 2);
        ps1 += __shfl_xor_sync(0xffffffffu, ps1, 1);
        ps1 += __shfl_xor_sync(0xffffffffu, ps1, 2);
        li0 = li0 * corr0 + ps0; mi0 = nm0;
        li1 = li1 * corr1 + ps1; mi1 = nm1;
        #pragma unroll
        for (int nt = 0; nt < 8; nt++) {
            accO[nt][0] *= corr0; accO[nt][1] *= corr0;
            accO[nt][2] *= corr1; accO[nt][3] *= corr1;
        }

        // P (with pv fold) -> smem
        #pragma unroll
        for (int nt = 0; nt < 8; nt++) {
            float2 pw = *(const float2*)(pvs + nt * 8 + 2 * j);
            ((__half2*)uP)[(w * 16 + g) * AT_SROW + nt * 4 + j] =
                __floats2half2_rn(accS[nt][0] * pw.x, accS[nt][1] * pw.y);
            ((__half2*)uP)[(w * 16 + g + 8) * AT_SROW + nt * 4 + j] =
                __floats2half2_rn(accS[nt][2] * pw.x, accS[nt][3] * pw.y);
        }
        __syncwarp();

        // O += P @ Vraw  (B fragment via ldmatrix.trans on V[m][d])
        #pragma unroll
        for (int ks = 0; ks < 4; ks++) {
            int k = ks * 8;
            uint32_t a[4];
            int r0 = (w * 16 + g) * AT_SROW, r1 = (w * 16 + g + 8) * AT_SROW;
            a[0] = uP[r0 + k + j];
            a[1] = uP[r1 + k + j];
            a[2] = uP[r0 + k + j + 4];
            a[3] = uP[r1 + k + j + 4];
            uint32_t vrow = sV + (uint32_t)(ks * 16 + (lane & 15)) * (AT_SROW * 4);
            #pragma unroll
            for (int nt = 0; nt < 8; nt++) {
                uint32_t bfr[2];
                ldsm_x2_trans(bfr, vrow + nt * 16);
                mma_fp16(accO[nt], a, bfr);
            }
        }
    }

    float inv0 = 1.f / li0, inv1 = 1.f / li1;
    int row0 = b * 1024 + n0 + w * 16 + g;
    #pragma unroll
    for (int nt = 0; nt < 8; nt++) {
        int col = h * 64 + nt * 8 + 2 * j;
        *(__half2*)(g_attnh + (size_t)row0 * HIDD + col) =
            __floats2half2_rn(accO[nt][0] * inv0, accO[nt][1] * inv0);
        *(__half2*)(g_attnh + (size_t)(row0 + 8) * HIDD + col) =
            __floats2half2_rn(accO[nt][2] * inv1, accO[nt][3] * inv1);
    }
}

// ---------------- K5: attn epilogue + residual + second x_cond ----------------
__global__ __launch_bounds__(256) void post_attn_kernel(const float* __restrict__ x,
                                                        const float* __restrict__ attn_gain) {
    int r = blockIdx.x, b = r >> 10;
    int e = threadIdx.x * 4;
    const __half* yr = g_tmph + (size_t)r * HIDD;
    float2 y01 = __half22float2(*(const __half2*)(yr + e));
    float2 y23 = __half22float2(*(const __half2*)(yr + e + 2));
    float ss = 0.f;
    const float* sp = g_ssp + (size_t)r * 64;
    #pragma unroll
    for (int p = 0; p < 16; p++) ss += sp[p];
    float py = rsqrtf(ss * (1.f / 1024.f) + 1e-4f) * expf(attn_gain[0]);
    float4 xv = *(const float4*)(x + (size_t)r * HIDD + e);
    float4 x1;
    x1.x = (0.7f * xv.x + 0.3f * (y01.x * py)) * RSQRT058;
    x1.y = (0.7f * xv.y + 0.3f * (y01.y * py)) * RSQRT058;
    x1.z = (0.7f * xv.z + 0.3f * (y23.x * py)) * RSQRT058;
    x1.w = (0.7f * xv.w + 0.3f * (y23.y * py)) * RSQRT058;
    *(float4*)(g_x1 + (size_t)r * HIDD + e) = x1;
    __shared__ float red[32];
    float ss1 = x1.x * x1.x + x1.y * x1.y + x1.z * x1.z + x1.w * x1.w;
    ss1 = block_reduce_sum(ss1, red);
    float p1 = rsqrtf(ss1 * (1.f / 1024.f) + 1e-4f);
    const float* gn = g_gain + b * 1024; const float* sh = g_shift + b * 1024;
    float o0 = x1.x * p1 * (1.f + gn[e + 0]) + sh[e + 0];
    float o1 = x1.y * p1 * (1.f + gn[e + 1]) + sh[e + 1];
    float o2 = x1.z * p1 * (1.f + gn[e + 2]) + sh[e + 2];
    float o3 = x1.w * p1 * (1.f + gn[e + 3]) + sh[e + 3];
    __half2* dst = (__half2*)(g_xcondh + (size_t)r * HIDD + e);
    dst[0] = __floats2half2_rn(o0, o1);
    dst[1] = __floats2half2_rn(o2, o3);
}

// ---------------- K6: MLP hidden activation (in-place fp16) ----------------
__global__ __launch_bounds__(256) void mlp_act_kernel() {
    int r = blockIdx.x;
    __half* row = g_hh + (size_t)r * MLPD;
    float ss = 0.f;
    const float* sp = g_ssp + (size_t)r * 64;
    #pragma unroll
    for (int p = 0; p < 64; p++) ss += sp[p];
    float ps = rsqrtf(ss * (1.f / 4096.f) + 1e-4f);
    int e = threadIdx.x * 16;
    uint4 d0 = *(const uint4*)(row + e);
    uint4 d1 = *(const uint4*)(row + e + 8);
    __half2* h0 = (__half2*)&d0;
    __half2* h1 = (__half2*)&d1;
    #pragma unroll
    for (int i = 0; i < 4; i++) {
        float2 a = __half22float2(h0[i]);
        float2 bq = __half22float2(h1[i]);
        float u0 = a.x * ps, u1 = a.y * ps, u2 = bq.x * ps, u3 = bq.y * ps;
        h0[i] = __floats2half2_rn(u0 / (1.f + expf(-u0)) * INV_0596,
                                  u1 / (1.f + expf(-u1)) * INV_0596);
        h1[i] = __floats2half2_rn(u2 / (1.f + expf(-u2)) * INV_0596,
                                  u3 / (1.f + expf(-u3)) * INV_0596);
    }
    *(uint4*)(row + e) = d0;
    *(uint4*)(row + e + 8) = d1;
}

// ---------------- K7: final epilogue ----------------
__global__ __launch_bounds__(256) void final_kernel(const float* __restrict__ mlp_gain,
                                                    float* __restrict__ out) {
    int r = blockIdx.x;
    int e = threadIdx.x * 4;
    const __half* yr = g_tmph + (size_t)r * HIDD;
    float2 y01 = __half22float2(*(const __half2*)(yr + e));
    float2 y23 = __half22float2(*(const __half2*)(yr + e + 2));
    float ss = 0.f;
    const float* sp = g_ssp + (size_t)r * 64;
    #pragma unroll
    for (int p = 0; p < 16; p++) ss += sp[p];
    float pm = rsqrtf(ss * (1.f / 1024.f) + 1e-4f) * expf(mlp_gain[0]);
    float4 x1 = *(const float4*)(g_x1 + (size_t)r * HIDD + e);
    float4 o;
    o.x = (0.7f * x1.x + 0.3f * (y01.x * pm)) * RSQRT058;
    o.y = (0.7f * x1.y + 0.3f * (y01.y * pm)) * RSQRT058;
    o.z = (0.7f * x1.z + 0.3f * (y23.x * pm)) * RSQRT058;
    o.w = (0.7f * x1.w + 0.3f * (y23.y * pm)) * RSQRT058;
    *(float4*)(out + (size_t)r * HIDD + e) = o;
}

// ---------------- launch ----------------
extern "C" void kernel_launch(void* const* d_in, const int* in_sizes, int n_in,
                              void* d_out, int out_size) {
    const float* x        = (const float*)d_in[0];
    const float* c        = (const float*)d_in[1];
    const float* w_cond   = (const float*)d_in[2];
    const float* w_qkv    = (const float*)d_in[3];
    const float* w_out    = (const float*)d_in[4];
    const float* w_mlp1   = (const float*)d_in[5];
    const float* w_mlp2   = (const float*)d_in[6];
    const float* attn_gain = (const float*)d_in[7];
    const float* mlp_gain  = (const float*)d_in[8];
    float* out = (float*)d_out;

    void* p;
    cudaGetSymbolAddress(&p, g_xcondh); __half* xcondh = (__half*)p;
    cudaGetSymbolAddress(&p, g_qkvh);   __half* qkvh  = (__half*)p;
    cudaGetSymbolAddress(&p, g_attnh);  __half* attnh = (__half*)p;
    cudaGetSymbolAddress(&p, g_tmph);   __half* tmph  = (__half*)p;
    cudaGetSymbolAddress(&p, g_hh);     __half* hh    = (__half*)p;
    cudaGetSymbolAddress(&p, g_ssp);    float* ssp    = (float*)p;
    cudaGetSymbolAddress(&p, g_s_qkv);  float* sqkv   = (float*)p;
    cudaGetSymbolAddress(&p, g_s_out);  float* sout   = (float*)p;
    cudaGetSymbolAddress(&p, g_s_mlp1); float* smlp1  = (float*)p;
    cudaGetSymbolAddress(&p, g_s_mlp2); float* smlp2  = (float*)p;
    cudaGetSymbolAddress(&p, g_wtq);    __half* wtq   = (__half*)p;
    cudaGetSymbolAddress(&p, g_wto);    __half* wto   = (__half*)p;
    cudaGetSymbolAddress(&p, g_wt1);    __half* wt1   = (__half*)p;
    cudaGetSymbolAddress(&p, g_wt2);    __half* wt2   = (__half*)p;

    cudaFuncSetAttribute(attn_mma_kernel, cudaFuncAttributeMaxDynamicSharedMemorySize,
                         ATT_SMEM_BYTES);
    cudaFuncSetAttribute(gemm_mma_kernel, cudaFuncAttributeMaxDynamicSharedMemorySize,
                         GEMM_SMEM_BYTES);

    scales_kernel<<<8192, 128>>>(w_cond, w_qkv, w_out, w_mlp1, w_mlp2);
    cond_part_kernel<<<dim3(8, 16), 256>>>(c, w_cond);
    cond_reduce_kernel<<<32, 256>>>();
    transpose_scale_kernel<<<dim3(3072 / 32, 1024 / 32), 256>>>(w_qkv, sqkv, wtq, 1024, 3072);
    transpose_scale_kernel<<<dim3(1024 / 32, 1024 / 32), 256>>>(w_out, sout, wto, 1024, 1024);
    transpose_scale_kernel<<<dim3(4096 / 32, 1024 / 32), 256>>>(w_mlp1, smlp1, wt1, 1024, 4096);
    transpose_scale_kernel<<<dim3(1024 / 32, 4096 / 32), 256>>>(w_mlp2, smlp2, wt2, 4096, 1024);

    xcond_kernel<<<4096, 256>>>(x);
    gemm_mma_kernel<<<dim3(12, 32), 256, GEMM_SMEM_BYTES>>>(xcondh, wtq, qkvh, nullptr,
                                                            4096, 3072, 1024);
    qkvnorm_kernel<<<4096, 256>>>();
    attn_mma_kernel<<<dim3(16, 64), 128, ATT_SMEM_BYTES>>>();
    gemm_mma_kernel<<<dim3(4, 32), 256, GEMM_SMEM_BYTES>>>(attnh, wto, tmph, ssp,
                                                           4096, 1024, 1024);
    post_attn_kernel<<<4096, 256>>>(x, attn_gain);
    gemm_mma_kernel<<<dim3(16, 32), 256, GEMM_SMEM_BYTES>>>(xcondh, wt1, hh, ssp,
                                                            4096, 4096, 1024);
    mlp_act_kernel<<<4096, 256>>>();
    gemm_mma_kernel<<<dim3(4, 32), 256, GEMM_SMEM_BYTES>>>(hh, wt2, tmph, ssp,
                                                           4096, 1024, 4096);
    final_kernel<<<4096, 256>>>(mlp_gain, out);
}